// round 1
// baseline (speedup 1.0000x reference)
#include <cuda_runtime.h>
#include <math.h>

// Problem constants
#define B_ 8
#define T_ 2048
#define C_ 384
#define H_ 6
#define D_ 64
#define M_ (B_*T_)          // 16384 rows
#define HALF_ 32            // D/2

// ---------------- scratch (static device globals; no allocation) ----------------
__device__ float g_qt[(size_t)M_ * C_];   // x @ Wq^T   [M, C]
__device__ float g_kt[(size_t)M_ * C_];
__device__ float g_vt[(size_t)M_ * C_];
__device__ float g_qh[(size_t)B_ * H_ * T_ * D_];  // [B*H, T, D] after rope+rms
__device__ float g_kh[(size_t)B_ * H_ * T_ * D_];
__device__ float g_vh[(size_t)B_ * H_ * T_ * D_];
__device__ float g_yt[(size_t)M_ * C_];   // attention output [M, C]

// ---------------- SGEMM: C[M,N] = A[M,K] * B[N,K]^T (both K-major) ----------------
#define GBM 64
#define GBN 64
#define GBK 32

__global__ __launch_bounds__(256) void sgemm_nt(const float* __restrict__ A,
                                                const float* __restrict__ Bm,
                                                float* __restrict__ Cm,
                                                int M, int N, int K)
{
    __shared__ __align__(16) float As[GBK][GBM];
    __shared__ __align__(16) float Bs[GBK][GBN];

    const int tid = threadIdx.x;
    const int m0 = blockIdx.y * GBM;
    const int n0 = blockIdx.x * GBN;

    const int lr = tid >> 2;          // 0..63 : tile row for loads
    const int lc = (tid & 3) * 8;     // 0,8,16,24 : k offset for loads

    const int ty = tid >> 4;          // 0..15
    const int tx = tid & 15;          // 0..15

    float c[4][4];
#pragma unroll
    for (int i = 0; i < 4; i++)
#pragma unroll
        for (int j = 0; j < 4; j++) c[i][j] = 0.f;

    for (int k0 = 0; k0 < K; k0 += GBK) {
        // global loads (coalesced float4 x2 per operand)
        const float4 a0 = *(const float4*)(A  + (size_t)(m0 + lr) * K + k0 + lc);
        const float4 a1 = *(const float4*)(A  + (size_t)(m0 + lr) * K + k0 + lc + 4);
        const float4 b0 = *(const float4*)(Bm + (size_t)(n0 + lr) * K + k0 + lc);
        const float4 b1 = *(const float4*)(Bm + (size_t)(n0 + lr) * K + k0 + lc + 4);

        __syncthreads();  // previous compute done before smem overwrite

        As[lc+0][lr] = a0.x; As[lc+1][lr] = a0.y; As[lc+2][lr] = a0.z; As[lc+3][lr] = a0.w;
        As[lc+4][lr] = a1.x; As[lc+5][lr] = a1.y; As[lc+6][lr] = a1.z; As[lc+7][lr] = a1.w;
        Bs[lc+0][lr] = b0.x; Bs[lc+1][lr] = b0.y; Bs[lc+2][lr] = b0.z; Bs[lc+3][lr] = b0.w;
        Bs[lc+4][lr] = b1.x; Bs[lc+5][lr] = b1.y; Bs[lc+6][lr] = b1.z; Bs[lc+7][lr] = b1.w;

        __syncthreads();

#pragma unroll
        for (int kk = 0; kk < GBK; kk++) {
            const float4 av = *(const float4*)(&As[kk][ty * 4]);
            const float4 bv = *(const float4*)(&Bs[kk][tx * 4]);
            const float a[4] = {av.x, av.y, av.z, av.w};
            const float b[4] = {bv.x, bv.y, bv.z, bv.w};
#pragma unroll
            for (int i = 0; i < 4; i++)
#pragma unroll
                for (int j = 0; j < 4; j++)
                    c[i][j] += a[i] * b[j];
        }
    }

#pragma unroll
    for (int i = 0; i < 4; i++) {
        float4 outv = make_float4(c[i][0], c[i][1], c[i][2], c[i][3]);
        *(float4*)(Cm + (size_t)(m0 + ty * 4 + i) * N + n0 + tx * 4) = outv;
    }
}

// ---------------- RoPE + RMS-norm + transpose to [B*H, T, D] ----------------
// One warp handles one (b, t, h) row of 64 elements for q, k and v.
__global__ __launch_bounds__(256) void rope_rms_kernel(const float* __restrict__ cosp,
                                                       const float* __restrict__ sinp)
{
    const int gwarp = (blockIdx.x * blockDim.x + threadIdx.x) >> 5;
    const int lane  = threadIdx.x & 31;
    if (gwarp >= B_ * T_ * H_) return;

    const int h  = gwarp % H_;
    const int bt = gwarp / H_;           // b*T + t
    const int t  = bt % T_;
    const int b  = bt / T_;

    const size_t src_off = (size_t)bt * C_ + h * D_;
    const size_t dst_off = ((size_t)(b * H_ + h) * T_ + t) * D_;

    const float c = cosp[t * HALF_ + lane];
    const float s = sinp[t * HALF_ + lane];

    // Q: rope + rms
    {
        const float x1 = g_qt[src_off + lane];
        const float x2 = g_qt[src_off + lane + HALF_];
        const float y1 =  x1 * c + x2 * s;
        const float y2 = -x1 * s + x2 * c;
        float ss = y1 * y1 + y2 * y2;
#pragma unroll
        for (int o = 16; o; o >>= 1) ss += __shfl_xor_sync(0xffffffffu, ss, o);
        const float r = rsqrtf(ss * (1.f / 64.f) + 1e-5f);
        g_qh[dst_off + lane]         = y1 * r;
        g_qh[dst_off + lane + HALF_] = y2 * r;
    }
    // K: rope + rms
    {
        const float x1 = g_kt[src_off + lane];
        const float x2 = g_kt[src_off + lane + HALF_];
        const float y1 =  x1 * c + x2 * s;
        const float y2 = -x1 * s + x2 * c;
        float ss = y1 * y1 + y2 * y2;
#pragma unroll
        for (int o = 16; o; o >>= 1) ss += __shfl_xor_sync(0xffffffffu, ss, o);
        const float r = rsqrtf(ss * (1.f / 64.f) + 1e-5f);
        g_kh[dst_off + lane]         = y1 * r;
        g_kh[dst_off + lane + HALF_] = y2 * r;
    }
    // V: plain transpose copy
    g_vh[dst_off + lane]         = g_vt[src_off + lane];
    g_vh[dst_off + lane + HALF_] = g_vt[src_off + lane + HALF_];
}

// ---------------- attention: flash-style, 1 query per thread ----------------
#define BQ 128
#define BKV 16

__global__ __launch_bounds__(128) void attn_kernel()
{
    __shared__ __align__(16) float4 Ks[BKV * 16];  // 16 keys x 16 float4 (D=64)
    __shared__ __align__(16) float4 Vs[BKV * 16];

    const int tid = threadIdx.x;
    const int bh  = blockIdx.y;                    // b*H + h
    const int qi  = blockIdx.x * BQ + tid;

    const float scale = 0.125f;                    // 1/sqrt(64)

    // load query into registers, pre-scaled
    float4 qr[16];
    const float4* qp = (const float4*)(g_qh + ((size_t)bh * T_ + qi) * D_);
#pragma unroll
    for (int i = 0; i < 16; i++) {
        float4 v = qp[i];
        v.x *= scale; v.y *= scale; v.z *= scale; v.w *= scale;
        qr[i] = v;
    }

    float4 acc[16];
#pragma unroll
    for (int i = 0; i < 16; i++) acc[i] = make_float4(0.f, 0.f, 0.f, 0.f);
    float m = -1e30f, l = 0.f;

    const float4* kbase = (const float4*)(g_kh + (size_t)bh * T_ * D_);
    const float4* vbase = (const float4*)(g_vh + (size_t)bh * T_ * D_);

    for (int kc = 0; kc < T_; kc += BKV) {
        __syncthreads();
        // 16 keys * 64 floats = 256 float4 per buffer; 128 threads -> 2 each (coalesced)
        const int cbase = kc * 16;  // float4 offset of chunk start
        Ks[tid]       = kbase[cbase + tid];
        Ks[tid + 128] = kbase[cbase + tid + 128];
        Vs[tid]       = vbase[cbase + tid];
        Vs[tid + 128] = vbase[cbase + tid + 128];
        __syncthreads();

        float sc[BKV];
#pragma unroll
        for (int j = 0; j < BKV; j++) {
            float s0 = 0.f, s1 = 0.f;
#pragma unroll
            for (int i = 0; i < 8; i++) {
                const float4 kv = Ks[j * 16 + i];
                s0 += qr[i].x * kv.x + qr[i].y * kv.y + qr[i].z * kv.z + qr[i].w * kv.w;
            }
#pragma unroll
            for (int i = 8; i < 16; i++) {
                const float4 kv = Ks[j * 16 + i];
                s1 += qr[i].x * kv.x + qr[i].y * kv.y + qr[i].z * kv.z + qr[i].w * kv.w;
            }
            sc[j] = s0 + s1;
        }

        float mx = m;
#pragma unroll
        for (int j = 0; j < BKV; j++) mx = fmaxf(mx, sc[j]);

        const float corr = __expf(m - mx);
        m = mx;
        l *= corr;
#pragma unroll
        for (int i = 0; i < 16; i++) {
            acc[i].x *= corr; acc[i].y *= corr; acc[i].z *= corr; acc[i].w *= corr;
        }

#pragma unroll
        for (int j = 0; j < BKV; j++) {
            const float p = __expf(sc[j] - m);
            l += p;
#pragma unroll
            for (int i = 0; i < 16; i++) {
                const float4 vv = Vs[j * 16 + i];
                acc[i].x += p * vv.x;
                acc[i].y += p * vv.y;
                acc[i].z += p * vv.z;
                acc[i].w += p * vv.w;
            }
        }
    }

    const float inv = 1.f / l;
    const int b = bh / H_;
    const int h = bh % H_;
    float4* yp = (float4*)(g_yt + ((size_t)(b * T_ + qi)) * C_ + h * D_);
#pragma unroll
    for (int i = 0; i < 16; i++) {
        float4 o = acc[i];
        o.x *= inv; o.y *= inv; o.z *= inv; o.w *= inv;
        yp[i] = o;
    }
}

// ---------------- launch ----------------
extern "C" void kernel_launch(void* const* d_in, const int* in_sizes, int n_in,
                              void* d_out, int out_size)
{
    const float* x    = (const float*)d_in[0];
    const float* Wq   = (const float*)d_in[1];
    const float* Wk   = (const float*)d_in[2];
    const float* Wv   = (const float*)d_in[3];
    const float* Wo   = (const float*)d_in[4];
    const float* cosp = (const float*)d_in[5];
    const float* sinp = (const float*)d_in[6];
    float* out = (float*)d_out;

    void *p_qt, *p_kt, *p_vt, *p_yt;
    cudaGetSymbolAddress(&p_qt, g_qt);
    cudaGetSymbolAddress(&p_kt, g_kt);
    cudaGetSymbolAddress(&p_vt, g_vt);
    cudaGetSymbolAddress(&p_yt, g_yt);

    dim3 gg(C_ / GBN, M_ / GBM);   // (6, 256)
    sgemm_nt<<<gg, 256>>>(x, Wq, (float*)p_qt, M_, C_, C_);
    sgemm_nt<<<gg, 256>>>(x, Wk, (float*)p_kt, M_, C_, C_);
    sgemm_nt<<<gg, 256>>>(x, Wv, (float*)p_vt, M_, C_, C_);

    const int rows = B_ * T_ * H_;            // 98304 warps
    rope_rms_kernel<<<rows / 8, 256>>>(cosp, sinp);

    dim3 ga(T_ / BQ, B_ * H_);                // (16, 48)
    attn_kernel<<<ga, 128>>>();

    sgemm_nt<<<gg, 256>>>((const float*)p_yt, Wo, out, M_, C_, C_);
}

// round 2
// speedup vs baseline: 1.6481x; 1.6481x over previous
#include <cuda_runtime.h>
#include <math.h>

// Problem constants
#define B_ 8
#define T_ 2048
#define C_ 384
#define H_ 6
#define D_ 64
#define M_ (B_*T_)          // 16384 rows
#define HALF_ 32            // D/2

typedef unsigned long long u64;

// ---------------- f32x2 packed helpers ----------------
__device__ __forceinline__ u64 fma2(u64 a, u64 b, u64 c) {
    u64 d;
    asm("fma.rn.f32x2 %0, %1, %2, %3;" : "=l"(d) : "l"(a), "l"(b), "l"(c));
    return d;
}
__device__ __forceinline__ u64 mul2(u64 a, u64 b) {
    u64 d;
    asm("mul.rn.f32x2 %0, %1, %2;" : "=l"(d) : "l"(a), "l"(b));
    return d;
}
__device__ __forceinline__ u64 add2(u64 a, u64 b) {
    u64 d;
    asm("add.rn.f32x2 %0, %1, %2;" : "=l"(d) : "l"(a), "l"(b));
    return d;
}
__device__ __forceinline__ u64 pack2(float lo, float hi) {
    u64 d;
    asm("mov.b64 %0, {%1, %2};" : "=l"(d) : "f"(lo), "f"(hi));
    return d;
}
__device__ __forceinline__ void unpack2(u64 v, float& lo, float& hi) {
    asm("mov.b64 {%0, %1}, %2;" : "=f"(lo), "=f"(hi) : "l"(v));
}

// ---------------- scratch (static device globals; no allocation) ----------------
__device__ float g_qt[(size_t)M_ * C_];   // x @ Wq^T   [M, C]
__device__ float g_kt[(size_t)M_ * C_];
__device__ float g_vt[(size_t)M_ * C_];
__device__ float g_qh[(size_t)B_ * H_ * T_ * D_];  // [B*H, T, D] after rope+rms
__device__ float g_kh[(size_t)B_ * H_ * T_ * D_];
__device__ float g_vh[(size_t)B_ * H_ * T_ * D_];
__device__ float g_yt[(size_t)M_ * C_];   // attention output [M, C]

// ---------------- SGEMM: C[M,N] = A[M,K] * B[N,K]^T, f32x2 core ----------------
// Tile 128x64x32, 256 threads, per-thread 8 rows x 4 cols (rows packed in pairs).
#define GBM 128
#define GBN 64
#define GBK 32

__global__ __launch_bounds__(256) void sgemm_nt(const float* __restrict__ A,
                                                const float* __restrict__ Bm,
                                                float* __restrict__ Cm,
                                                int M, int N, int K)
{
    __shared__ __align__(16) float As[GBK][GBM];
    __shared__ __align__(16) float Bs[GBK][GBN];

    const int tid = threadIdx.x;
    const int m0 = blockIdx.y * GBM;
    const int n0 = blockIdx.x * GBN;

    // global-load mapping
    const int ar = tid >> 1;                 // 0..127 A row
    const int ak = (tid & 1) * 16;           // 0 or 16
    const int br = tid >> 2;                 // 0..63 B row
    const int bk = (tid & 3) * 8;            // 0,8,16,24

    // compute mapping
    const int ty = tid >> 4;                 // 0..15 -> rows ty*8..+7
    const int tx = tid & 15;                 // 0..15 -> cols tx*4..+3

    u64 c2[4][4];                            // [row-pair][col], lane0=even row
#pragma unroll
    for (int i = 0; i < 4; i++)
#pragma unroll
        for (int j = 0; j < 4; j++) c2[i][j] = 0ull;

    for (int k0 = 0; k0 < K; k0 += GBK) {
        float4 av[4], bv[2];
#pragma unroll
        for (int p = 0; p < 4; p++)
            av[p] = *(const float4*)(A + (size_t)(m0 + ar) * K + k0 + ak + p * 4);
#pragma unroll
        for (int p = 0; p < 2; p++)
            bv[p] = *(const float4*)(Bm + (size_t)(n0 + br) * K + k0 + bk + p * 4);

        __syncthreads();

#pragma unroll
        for (int p = 0; p < 4; p++) {
            As[ak + p*4 + 0][ar] = av[p].x;
            As[ak + p*4 + 1][ar] = av[p].y;
            As[ak + p*4 + 2][ar] = av[p].z;
            As[ak + p*4 + 3][ar] = av[p].w;
        }
#pragma unroll
        for (int p = 0; p < 2; p++) {
            Bs[bk + p*4 + 0][br] = bv[p].x;
            Bs[bk + p*4 + 1][br] = bv[p].y;
            Bs[bk + p*4 + 2][br] = bv[p].z;
            Bs[bk + p*4 + 3][br] = bv[p].w;
        }

        __syncthreads();

#pragma unroll
        for (int kk = 0; kk < GBK; kk++) {
            // A: 8 consecutive rows = 4 natural f32x2 pairs
            const ulonglong2 a01 = *(const ulonglong2*)(&As[kk][ty * 8]);
            const ulonglong2 a23 = *(const ulonglong2*)(&As[kk][ty * 8 + 4]);
            const u64 ap[4] = {a01.x, a01.y, a23.x, a23.y};
            // B: 4 cols, each duplicated into both lanes
            const float4 b4 = *(const float4*)(&Bs[kk][tx * 4]);
            const u64 bd[4] = {pack2(b4.x, b4.x), pack2(b4.y, b4.y),
                               pack2(b4.z, b4.z), pack2(b4.w, b4.w)};
#pragma unroll
            for (int i = 0; i < 4; i++)
#pragma unroll
                for (int j = 0; j < 4; j++)
                    c2[i][j] = fma2(ap[i], bd[j], c2[i][j]);
        }
    }

    // epilogue: unpack row pairs -> 8 float4 stores
#pragma unroll
    for (int i = 0; i < 4; i++) {
        float r0[4], r1[4];
#pragma unroll
        for (int j = 0; j < 4; j++) unpack2(c2[i][j], r0[j], r1[j]);
        *(float4*)(Cm + (size_t)(m0 + ty*8 + i*2 + 0) * N + n0 + tx*4) =
            make_float4(r0[0], r0[1], r0[2], r0[3]);
        *(float4*)(Cm + (size_t)(m0 + ty*8 + i*2 + 1) * N + n0 + tx*4) =
            make_float4(r1[0], r1[1], r1[2], r1[3]);
    }
}

// ---------------- RoPE + RMS-norm + transpose to [B*H, T, D] ----------------
__global__ __launch_bounds__(256) void rope_rms_kernel(const float* __restrict__ cosp,
                                                       const float* __restrict__ sinp)
{
    const int gwarp = (blockIdx.x * blockDim.x + threadIdx.x) >> 5;
    const int lane  = threadIdx.x & 31;
    if (gwarp >= B_ * T_ * H_) return;

    const int h  = gwarp % H_;
    const int bt = gwarp / H_;           // b*T + t
    const int t  = bt % T_;
    const int b  = bt / T_;

    const size_t src_off = (size_t)bt * C_ + h * D_;
    const size_t dst_off = ((size_t)(b * H_ + h) * T_ + t) * D_;

    const float c = cosp[t * HALF_ + lane];
    const float s = sinp[t * HALF_ + lane];

    {
        const float x1 = g_qt[src_off + lane];
        const float x2 = g_qt[src_off + lane + HALF_];
        const float y1 =  x1 * c + x2 * s;
        const float y2 = -x1 * s + x2 * c;
        float ss = y1 * y1 + y2 * y2;
#pragma unroll
        for (int o = 16; o; o >>= 1) ss += __shfl_xor_sync(0xffffffffu, ss, o);
        const float r = rsqrtf(ss * (1.f / 64.f) + 1e-5f);
        g_qh[dst_off + lane]         = y1 * r;
        g_qh[dst_off + lane + HALF_] = y2 * r;
    }
    {
        const float x1 = g_kt[src_off + lane];
        const float x2 = g_kt[src_off + lane + HALF_];
        const float y1 =  x1 * c + x2 * s;
        const float y2 = -x1 * s + x2 * c;
        float ss = y1 * y1 + y2 * y2;
#pragma unroll
        for (int o = 16; o; o >>= 1) ss += __shfl_xor_sync(0xffffffffu, ss, o);
        const float r = rsqrtf(ss * (1.f / 64.f) + 1e-5f);
        g_kh[dst_off + lane]         = y1 * r;
        g_kh[dst_off + lane + HALF_] = y2 * r;
    }
    g_vh[dst_off + lane]         = g_vt[src_off + lane];
    g_vh[dst_off + lane + HALF_] = g_vt[src_off + lane + HALF_];
}

// ---------------- attention: flash-style, 1 query per thread, f32x2 core ----------------
#define BQ 128
#define BKV 16

__global__ __launch_bounds__(128) void attn_kernel()
{
    // 16 keys x 64 floats = 16 ulonglong2 per key
    __shared__ __align__(16) ulonglong2 Ks[BKV * 16];
    __shared__ __align__(16) ulonglong2 Vs[BKV * 16];

    const int tid = threadIdx.x;
    const int bh  = blockIdx.y;                    // b*H + h
    const int qi  = blockIdx.x * BQ + tid;

    const float scale = 0.125f;                    // 1/sqrt(64)
    const u64 scale2 = pack2(scale, scale);

    // load query (32 packed f32x2), pre-scaled
    u64 q2[32];
    const ulonglong2* qp = (const ulonglong2*)(g_qh + ((size_t)bh * T_ + qi) * D_);
#pragma unroll
    for (int i = 0; i < 16; i++) {
        ulonglong2 v = qp[i];
        q2[2*i]   = mul2(v.x, scale2);
        q2[2*i+1] = mul2(v.y, scale2);
    }

    u64 acc2[32];
#pragma unroll
    for (int i = 0; i < 32; i++) acc2[i] = 0ull;
    float m = -1e30f, l = 0.f;

    const ulonglong2* kbase = (const ulonglong2*)(g_kh + (size_t)bh * T_ * D_);
    const ulonglong2* vbase = (const ulonglong2*)(g_vh + (size_t)bh * T_ * D_);

    for (int kc = 0; kc < T_; kc += BKV) {
        __syncthreads();
        const int cbase = kc * 16;  // ulonglong2 offset of chunk start
        Ks[tid]       = kbase[cbase + tid];
        Ks[tid + 128] = kbase[cbase + tid + 128];
        Vs[tid]       = vbase[cbase + tid];
        Vs[tid + 128] = vbase[cbase + tid + 128];
        __syncthreads();

        float sc[BKV];
#pragma unroll
        for (int j = 0; j < BKV; j++) {
            u64 a0 = 0ull, a1 = 0ull, a2 = 0ull, a3 = 0ull;
#pragma unroll
            for (int i = 0; i < 16; i += 2) {
                const ulonglong2 kv0 = Ks[j * 16 + i];
                const ulonglong2 kv1 = Ks[j * 16 + i + 1];
                a0 = fma2(q2[2*i],   kv0.x, a0);
                a1 = fma2(q2[2*i+1], kv0.y, a1);
                a2 = fma2(q2[2*i+2], kv1.x, a2);
                a3 = fma2(q2[2*i+3], kv1.y, a3);
            }
            a0 = add2(a0, a1);
            a2 = add2(a2, a3);
            a0 = add2(a0, a2);
            float lo, hi;
            unpack2(a0, lo, hi);
            sc[j] = lo + hi;
        }

        float mx = m;
#pragma unroll
        for (int j = 0; j < BKV; j++) mx = fmaxf(mx, sc[j]);

        const float corr = __expf(m - mx);
        m = mx;
        l *= corr;
        const u64 corr2 = pack2(corr, corr);
#pragma unroll
        for (int i = 0; i < 32; i++) acc2[i] = mul2(acc2[i], corr2);

#pragma unroll
        for (int j = 0; j < BKV; j++) {
            const float p = __expf(sc[j] - m);
            l += p;
            const u64 pp = pack2(p, p);
#pragma unroll
            for (int i = 0; i < 16; i++) {
                const ulonglong2 vv = Vs[j * 16 + i];
                acc2[2*i]   = fma2(pp, vv.x, acc2[2*i]);
                acc2[2*i+1] = fma2(pp, vv.y, acc2[2*i+1]);
            }
        }
    }

    const float inv = 1.f / l;
    const int b = bh / H_;
    const int h = bh % H_;
    float4* yp = (float4*)(g_yt + ((size_t)(b * T_ + qi)) * C_ + h * D_);
#pragma unroll
    for (int i = 0; i < 16; i++) {
        float x0, x1, x2, x3;
        unpack2(acc2[2*i],   x0, x1);
        unpack2(acc2[2*i+1], x2, x3);
        yp[i] = make_float4(x0 * inv, x1 * inv, x2 * inv, x3 * inv);
    }
}

// ---------------- launch ----------------
extern "C" void kernel_launch(void* const* d_in, const int* in_sizes, int n_in,
                              void* d_out, int out_size)
{
    const float* x    = (const float*)d_in[0];
    const float* Wq   = (const float*)d_in[1];
    const float* Wk   = (const float*)d_in[2];
    const float* Wv   = (const float*)d_in[3];
    const float* Wo   = (const float*)d_in[4];
    const float* cosp = (const float*)d_in[5];
    const float* sinp = (const float*)d_in[6];
    float* out = (float*)d_out;

    void *p_qt, *p_kt, *p_vt, *p_yt;
    cudaGetSymbolAddress(&p_qt, g_qt);
    cudaGetSymbolAddress(&p_kt, g_kt);
    cudaGetSymbolAddress(&p_vt, g_vt);
    cudaGetSymbolAddress(&p_yt, g_yt);

    dim3 gg(C_ / GBN, M_ / GBM);   // (6, 128)
    sgemm_nt<<<gg, 256>>>(x, Wq, (float*)p_qt, M_, C_, C_);
    sgemm_nt<<<gg, 256>>>(x, Wk, (float*)p_kt, M_, C_, C_);
    sgemm_nt<<<gg, 256>>>(x, Wv, (float*)p_vt, M_, C_, C_);

    const int rows = B_ * T_ * H_;
    rope_rms_kernel<<<rows / 8, 256>>>(cosp, sinp);

    dim3 ga(T_ / BQ, B_ * H_);                // (16, 48)
    attn_kernel<<<ga, 128>>>();

    sgemm_nt<<<gg, 256>>>((const float*)p_yt, Wo, out, M_, C_, C_);
}

// round 3
// speedup vs baseline: 4.7701x; 2.8944x over previous
#include <cuda_runtime.h>
#include <math.h>

// Problem constants
#define B_ 8
#define T_ 2048
#define C_ 384
#define H_ 6
#define D_ 64
#define M_ (B_*T_)          // 16384 rows
#define HALF_ 32            // D/2

typedef unsigned long long u64;

// ---------------- f32x2 packed helpers ----------------
__device__ __forceinline__ u64 fma2(u64 a, u64 b, u64 c) {
    u64 d;
    asm("fma.rn.f32x2 %0, %1, %2, %3;" : "=l"(d) : "l"(a), "l"(b), "l"(c));
    return d;
}
__device__ __forceinline__ u64 pack2(float lo, float hi) {
    u64 d;
    asm("mov.b64 %0, {%1, %2};" : "=l"(d) : "f"(lo), "f"(hi));
    return d;
}
__device__ __forceinline__ void unpack2(u64 v, float& lo, float& hi) {
    asm("mov.b64 {%0, %1}, %2;" : "=f"(lo), "=f"(hi) : "l"(v));
}

// ---------------- tf32 mma helpers ----------------
__device__ __forceinline__ unsigned cvt_tf32(float x) {
    unsigned u;
    asm("cvt.rna.tf32.f32 %0, %1;" : "=r"(u) : "f"(x));
    return u;
}
__device__ __forceinline__ float tf32f(float x) {
    return __uint_as_float(cvt_tf32(x));
}
__device__ __forceinline__ float ex2f(float x) {
    float y;
    asm("ex2.approx.f32 %0, %1;" : "=f"(y) : "f"(x));
    return y;
}
__device__ __forceinline__ void mma8(float c[4], const unsigned a[4],
                                     unsigned b0, unsigned b1) {
    asm volatile(
        "mma.sync.aligned.m16n8k8.row.col.f32.tf32.tf32.f32 "
        "{%0,%1,%2,%3}, {%4,%5,%6,%7}, {%8,%9}, {%0,%1,%2,%3};"
        : "+f"(c[0]), "+f"(c[1]), "+f"(c[2]), "+f"(c[3])
        : "r"(a[0]), "r"(a[1]), "r"(a[2]), "r"(a[3]), "r"(b0), "r"(b1));
}

// ---------------- scratch ----------------
__device__ float g_qt[(size_t)M_ * C_];
__device__ float g_kt[(size_t)M_ * C_];
__device__ float g_vt[(size_t)M_ * C_];
__device__ float g_qh[(size_t)B_ * H_ * T_ * D_];
__device__ float g_kh[(size_t)B_ * H_ * T_ * D_];
__device__ float g_vh[(size_t)B_ * H_ * T_ * D_];
__device__ float g_yt[(size_t)M_ * C_];

// ---------------- SGEMM: C[M,N] = A[M,K] * B[N,K]^T, f32x2 core ----------------
#define GBM 128
#define GBN 64
#define GBK 32

__global__ __launch_bounds__(256) void sgemm_nt(const float* __restrict__ A,
                                                const float* __restrict__ Bm,
                                                float* __restrict__ Cm,
                                                int M, int N, int K)
{
    __shared__ __align__(16) float As[GBK][GBM];
    __shared__ __align__(16) float Bs[GBK][GBN];

    const int tid = threadIdx.x;
    const int m0 = blockIdx.y * GBM;
    const int n0 = blockIdx.x * GBN;

    const int ar = tid >> 1;
    const int ak = (tid & 1) * 16;
    const int br = tid >> 2;
    const int bk = (tid & 3) * 8;

    const int ty = tid >> 4;
    const int tx = tid & 15;

    u64 c2[4][4];
#pragma unroll
    for (int i = 0; i < 4; i++)
#pragma unroll
        for (int j = 0; j < 4; j++) c2[i][j] = 0ull;

    for (int k0 = 0; k0 < K; k0 += GBK) {
        float4 av[4], bv[2];
#pragma unroll
        for (int p = 0; p < 4; p++)
            av[p] = *(const float4*)(A + (size_t)(m0 + ar) * K + k0 + ak + p * 4);
#pragma unroll
        for (int p = 0; p < 2; p++)
            bv[p] = *(const float4*)(Bm + (size_t)(n0 + br) * K + k0 + bk + p * 4);

        __syncthreads();

#pragma unroll
        for (int p = 0; p < 4; p++) {
            As[ak + p*4 + 0][ar] = av[p].x;
            As[ak + p*4 + 1][ar] = av[p].y;
            As[ak + p*4 + 2][ar] = av[p].z;
            As[ak + p*4 + 3][ar] = av[p].w;
        }
#pragma unroll
        for (int p = 0; p < 2; p++) {
            Bs[bk + p*4 + 0][br] = bv[p].x;
            Bs[bk + p*4 + 1][br] = bv[p].y;
            Bs[bk + p*4 + 2][br] = bv[p].z;
            Bs[bk + p*4 + 3][br] = bv[p].w;
        }

        __syncthreads();

#pragma unroll
        for (int kk = 0; kk < GBK; kk++) {
            const ulonglong2 a01 = *(const ulonglong2*)(&As[kk][ty * 8]);
            const ulonglong2 a23 = *(const ulonglong2*)(&As[kk][ty * 8 + 4]);
            const u64 ap[4] = {a01.x, a01.y, a23.x, a23.y};
            const float4 b4 = *(const float4*)(&Bs[kk][tx * 4]);
            const u64 bd[4] = {pack2(b4.x, b4.x), pack2(b4.y, b4.y),
                               pack2(b4.z, b4.z), pack2(b4.w, b4.w)};
#pragma unroll
            for (int i = 0; i < 4; i++)
#pragma unroll
                for (int j = 0; j < 4; j++)
                    c2[i][j] = fma2(ap[i], bd[j], c2[i][j]);
        }
    }

#pragma unroll
    for (int i = 0; i < 4; i++) {
        float r0[4], r1[4];
#pragma unroll
        for (int j = 0; j < 4; j++) unpack2(c2[i][j], r0[j], r1[j]);
        *(float4*)(Cm + (size_t)(m0 + ty*8 + i*2 + 0) * N + n0 + tx*4) =
            make_float4(r0[0], r0[1], r0[2], r0[3]);
        *(float4*)(Cm + (size_t)(m0 + ty*8 + i*2 + 1) * N + n0 + tx*4) =
            make_float4(r1[0], r1[1], r1[2], r1[3]);
    }
}

// ---------------- RoPE + RMS-norm + transpose ----------------
__global__ __launch_bounds__(256) void rope_rms_kernel(const float* __restrict__ cosp,
                                                       const float* __restrict__ sinp)
{
    const int gwarp = (blockIdx.x * blockDim.x + threadIdx.x) >> 5;
    const int lane  = threadIdx.x & 31;
    if (gwarp >= B_ * T_ * H_) return;

    const int h  = gwarp % H_;
    const int bt = gwarp / H_;
    const int t  = bt % T_;
    const int b  = bt / T_;

    const size_t src_off = (size_t)bt * C_ + h * D_;
    const size_t dst_off = ((size_t)(b * H_ + h) * T_ + t) * D_;

    const float c = cosp[t * HALF_ + lane];
    const float s = sinp[t * HALF_ + lane];

    {
        const float x1 = g_qt[src_off + lane];
        const float x2 = g_qt[src_off + lane + HALF_];
        const float y1 =  x1 * c + x2 * s;
        const float y2 = -x1 * s + x2 * c;
        float ss = y1 * y1 + y2 * y2;
#pragma unroll
        for (int o = 16; o; o >>= 1) ss += __shfl_xor_sync(0xffffffffu, ss, o);
        const float r = rsqrtf(ss * (1.f / 64.f) + 1e-5f);
        g_qh[dst_off + lane]         = y1 * r;
        g_qh[dst_off + lane + HALF_] = y2 * r;
    }
    {
        const float x1 = g_kt[src_off + lane];
        const float x2 = g_kt[src_off + lane + HALF_];
        const float y1 =  x1 * c + x2 * s;
        const float y2 = -x1 * s + x2 * c;
        float ss = y1 * y1 + y2 * y2;
#pragma unroll
        for (int o = 16; o; o >>= 1) ss += __shfl_xor_sync(0xffffffffu, ss, o);
        const float r = rsqrtf(ss * (1.f / 64.f) + 1e-5f);
        g_kh[dst_off + lane]         = y1 * r;
        g_kh[dst_off + lane + HALF_] = y2 * r;
    }
    g_vh[dst_off + lane]         = g_vt[src_off + lane];
    g_vh[dst_off + lane + HALF_] = g_vt[src_off + lane + HALF_];
}

// ---------------- attention: flash, tf32 mma.sync ----------------
// Block = 128 threads (4 warps), AQ=128 queries (warp handles m=32),
// KV tile = 64 keys. Q in registers, K/V/P in padded smem.
#define AQ 128
#define AK 64
#define KSTR 68
#define VSTR 72
#define PSTR 68
#define ASMEM ((64*KSTR + 64*VSTR + 4*32*PSTR) * 4)

__global__ __launch_bounds__(128) void attn_mma()
{
    extern __shared__ float smf[];
    float* Ks = smf;                        // [64][KSTR]  key-major
    float* Vs = smf + 64*KSTR;              // [64][VSTR]  key-major
    const int tid  = threadIdx.x;
    const int w    = tid >> 5;
    const int lane = tid & 31;
    const int gr   = lane >> 2;             // 0..7
    const int gc   = lane & 3;              // 0..3
    float* Ps = smf + 64*KSTR + 64*VSTR + w * (32*PSTR);  // per-warp [32][PSTR]

    const int bh = blockIdx.y;
    const int q0 = blockIdx.x * AQ + w * 32;

    const float* Qg = g_qh + ((size_t)bh * T_ + q0) * D_;
    const float* Kg = g_kh + (size_t)bh * T_ * D_;
    const float* Vg = g_vh + (size_t)bh * T_ * D_;

    // Q fragments (2 m-halves x 8 k-chunks), pre-scaled by 1/sqrt(D)*log2(e)
    const float qsc = 0.125f * 1.44269504088896340736f;
    unsigned qa[2][8][4];
#pragma unroll
    for (int hm = 0; hm < 2; hm++) {
        const float* qr0 = Qg + (hm*16 + gr) * D_;
        const float* qr1 = qr0 + 8 * D_;
#pragma unroll
        for (int kc = 0; kc < 8; kc++) {
            qa[hm][kc][0] = cvt_tf32(qr0[kc*8 + gc]     * qsc);
            qa[hm][kc][1] = cvt_tf32(qr1[kc*8 + gc]     * qsc);
            qa[hm][kc][2] = cvt_tf32(qr0[kc*8 + gc + 4] * qsc);
            qa[hm][kc][3] = cvt_tf32(qr1[kc*8 + gc + 4] * qsc);
        }
    }

    float o[2][8][4];
#pragma unroll
    for (int hm = 0; hm < 2; hm++)
#pragma unroll
        for (int nt = 0; nt < 8; nt++)
#pragma unroll
            for (int j = 0; j < 4; j++) o[hm][nt][j] = 0.f;

    float mrow[2][2] = {{-1e30f, -1e30f}, {-1e30f, -1e30f}};   // [half][row0/row1]
    float lrow[2][2] = {{0.f, 0.f}, {0.f, 0.f}};

    for (int s0 = 0; s0 < T_; s0 += AK) {
        __syncthreads();
        // Load K,V tile (64x64 each), tf32-rounded. 1024 float4 / 128 thr = 8 each.
#pragma unroll
        for (int i = tid; i < 1024; i += 128) {
            const int r = i >> 4, c = (i & 15) * 4;
            const float4 kq = *(const float4*)(Kg + (size_t)(s0 + r) * D_ + c);
            float* kd = Ks + r * KSTR + c;
            kd[0] = tf32f(kq.x); kd[1] = tf32f(kq.y);
            kd[2] = tf32f(kq.z); kd[3] = tf32f(kq.w);
            const float4 vq = *(const float4*)(Vg + (size_t)(s0 + r) * D_ + c);
            float* vd = Vs + r * VSTR + c;
            vd[0] = tf32f(vq.x); vd[1] = tf32f(vq.y);
            vd[2] = tf32f(vq.z); vd[3] = tf32f(vq.w);
        }
        __syncthreads();

        // ---- S = Q K^T (both m-halves share B loads) ----
        float sv[2][8][4];
#pragma unroll
        for (int hm = 0; hm < 2; hm++)
#pragma unroll
            for (int nt = 0; nt < 8; nt++)
#pragma unroll
                for (int j = 0; j < 4; j++) sv[hm][nt][j] = 0.f;

#pragma unroll
        for (int nt = 0; nt < 8; nt++) {
            const float* kb = Ks + (nt*8 + gr) * KSTR + gc;
            unsigned bl[8][2];
#pragma unroll
            for (int kc = 0; kc < 8; kc++) {
                bl[kc][0] = __float_as_uint(kb[kc*8]);
                bl[kc][1] = __float_as_uint(kb[kc*8 + 4]);
            }
#pragma unroll
            for (int kc = 0; kc < 8; kc++) mma8(sv[0][nt], qa[0][kc], bl[kc][0], bl[kc][1]);
#pragma unroll
            for (int kc = 0; kc < 8; kc++) mma8(sv[1][nt], qa[1][kc], bl[kc][0], bl[kc][1]);
        }

        // ---- online softmax per half (log2 domain) ----
        __syncwarp();
#pragma unroll
        for (int hm = 0; hm < 2; hm++) {
            float mx0 = -1e30f, mx1 = -1e30f;
#pragma unroll
            for (int nt = 0; nt < 8; nt++) {
                mx0 = fmaxf(mx0, fmaxf(sv[hm][nt][0], sv[hm][nt][1]));
                mx1 = fmaxf(mx1, fmaxf(sv[hm][nt][2], sv[hm][nt][3]));
            }
#pragma unroll
            for (int off = 1; off <= 2; off <<= 1) {
                mx0 = fmaxf(mx0, __shfl_xor_sync(0xffffffffu, mx0, off));
                mx1 = fmaxf(mx1, __shfl_xor_sync(0xffffffffu, mx1, off));
            }
            const float nm0 = fmaxf(mrow[hm][0], mx0);
            const float nm1 = fmaxf(mrow[hm][1], mx1);
            const float c0 = ex2f(mrow[hm][0] - nm0);
            const float c1 = ex2f(mrow[hm][1] - nm1);
            mrow[hm][0] = nm0; mrow[hm][1] = nm1;
            lrow[hm][0] *= c0; lrow[hm][1] *= c1;

            float rs0 = 0.f, rs1 = 0.f;
#pragma unroll
            for (int nt = 0; nt < 8; nt++) {
                const float p00 = ex2f(sv[hm][nt][0] - nm0);
                const float p01 = ex2f(sv[hm][nt][1] - nm0);
                const float p10 = ex2f(sv[hm][nt][2] - nm1);
                const float p11 = ex2f(sv[hm][nt][3] - nm1);
                rs0 += p00 + p01;
                rs1 += p10 + p11;
                float* pr0 = Ps + (hm*16 + gr) * PSTR + nt*8 + 2*gc;
                pr0[0] = tf32f(p00); pr0[1] = tf32f(p01);
                float* pr1 = pr0 + 8 * PSTR;
                pr1[0] = tf32f(p10); pr1[1] = tf32f(p11);
            }
#pragma unroll
            for (int off = 1; off <= 2; off <<= 1) {
                rs0 += __shfl_xor_sync(0xffffffffu, rs0, off);
                rs1 += __shfl_xor_sync(0xffffffffu, rs1, off);
            }
            lrow[hm][0] += rs0; lrow[hm][1] += rs1;
#pragma unroll
            for (int nt = 0; nt < 8; nt++) {
                o[hm][nt][0] *= c0; o[hm][nt][1] *= c0;
                o[hm][nt][2] *= c1; o[hm][nt][3] *= c1;
            }
        }
        __syncwarp();

        // ---- O += P V ----
#pragma unroll
        for (int kc = 0; kc < 8; kc++) {
            unsigned a0[4], a1[4];
            const float* pb = Ps + gr * PSTR + kc*8 + gc;
            a0[0] = __float_as_uint(pb[0]);
            a0[1] = __float_as_uint(pb[8*PSTR]);
            a0[2] = __float_as_uint(pb[4]);
            a0[3] = __float_as_uint(pb[8*PSTR + 4]);
            const float* pb1 = pb + 16*PSTR;
            a1[0] = __float_as_uint(pb1[0]);
            a1[1] = __float_as_uint(pb1[8*PSTR]);
            a1[2] = __float_as_uint(pb1[4]);
            a1[3] = __float_as_uint(pb1[8*PSTR + 4]);
#pragma unroll
            for (int nt = 0; nt < 8; nt++) {
                const float* vb = Vs + (kc*8 + gc) * VSTR + nt*8 + gr;
                const unsigned b0 = __float_as_uint(vb[0]);
                const unsigned b1 = __float_as_uint(vb[4*VSTR]);
                mma8(o[0][nt], a0, b0, b1);
                mma8(o[1][nt], a1, b0, b1);
            }
        }
        __syncwarp();
    }

    // ---- epilogue: normalize + scatter into g_yt [b*T+t][C] ----
    const int b = bh / H_;
    const int h = bh % H_;
#pragma unroll
    for (int hm = 0; hm < 2; hm++) {
        const float il0 = 1.f / lrow[hm][0];
        const float il1 = 1.f / lrow[hm][1];
        const int r0 = q0 + hm*16 + gr;
        const int r1 = r0 + 8;
#pragma unroll
        for (int nt = 0; nt < 8; nt++) {
            const int col = h * D_ + nt*8 + 2*gc;
            *(float2*)(g_yt + (size_t)(b * T_ + r0) * C_ + col) =
                make_float2(o[hm][nt][0] * il0, o[hm][nt][1] * il0);
            *(float2*)(g_yt + (size_t)(b * T_ + r1) * C_ + col) =
                make_float2(o[hm][nt][2] * il1, o[hm][nt][3] * il1);
        }
    }
}

// ---------------- launch ----------------
extern "C" void kernel_launch(void* const* d_in, const int* in_sizes, int n_in,
                              void* d_out, int out_size)
{
    const float* x    = (const float*)d_in[0];
    const float* Wq   = (const float*)d_in[1];
    const float* Wk   = (const float*)d_in[2];
    const float* Wv   = (const float*)d_in[3];
    const float* Wo   = (const float*)d_in[4];
    const float* cosp = (const float*)d_in[5];
    const float* sinp = (const float*)d_in[6];
    float* out = (float*)d_out;

    void *p_qt, *p_kt, *p_vt, *p_yt;
    cudaGetSymbolAddress(&p_qt, g_qt);
    cudaGetSymbolAddress(&p_kt, g_kt);
    cudaGetSymbolAddress(&p_vt, g_vt);
    cudaGetSymbolAddress(&p_yt, g_yt);

    static int smem_set = 0;
    if (!smem_set) {
        cudaFuncSetAttribute(attn_mma, cudaFuncAttributeMaxDynamicSharedMemorySize, ASMEM);
        smem_set = 1;
    }

    dim3 gg(C_ / GBN, M_ / GBM);   // (6, 128)
    sgemm_nt<<<gg, 256>>>(x, Wq, (float*)p_qt, M_, C_, C_);
    sgemm_nt<<<gg, 256>>>(x, Wk, (float*)p_kt, M_, C_, C_);
    sgemm_nt<<<gg, 256>>>(x, Wv, (float*)p_vt, M_, C_, C_);

    const int rows = B_ * T_ * H_;
    rope_rms_kernel<<<rows / 8, 256>>>(cosp, sinp);

    dim3 ga(T_ / AQ, B_ * H_);                // (16, 48)
    attn_mma<<<ga, 128, ASMEM>>>();

    sgemm_nt<<<gg, 256>>>((const float*)p_yt, Wo, out, M_, C_, C_);
}

// round 4
// speedup vs baseline: 7.1050x; 1.4895x over previous
#include <cuda_runtime.h>
#include <math.h>

// Problem constants
#define B_ 8
#define T_ 2048
#define C_ 384
#define H_ 6
#define D_ 64
#define M_ (B_*T_)          // 16384 rows
#define HALF_ 32            // D/2

typedef unsigned long long u64;

// ---------------- tf32 mma helpers ----------------
__device__ __forceinline__ unsigned cvt_tf32(float x) {
    unsigned u;
    asm("cvt.rna.tf32.f32 %0, %1;" : "=r"(u) : "f"(x));
    return u;
}
__device__ __forceinline__ float tf32f(float x) {
    return __uint_as_float(cvt_tf32(x));
}
__device__ __forceinline__ float ex2f(float x) {
    float y;
    asm("ex2.approx.f32 %0, %1;" : "=f"(y) : "f"(x));
    return y;
}
__device__ __forceinline__ void mma8(float c[4], const unsigned a[4],
                                     unsigned b0, unsigned b1) {
    asm volatile(
        "mma.sync.aligned.m16n8k8.row.col.f32.tf32.tf32.f32 "
        "{%0,%1,%2,%3}, {%4,%5,%6,%7}, {%8,%9}, {%0,%1,%2,%3};"
        : "+f"(c[0]), "+f"(c[1]), "+f"(c[2]), "+f"(c[3])
        : "r"(a[0]), "r"(a[1]), "r"(a[2]), "r"(a[3]), "r"(b0), "r"(b1));
}

// ---------------- scratch ----------------
__device__ float g_qt[(size_t)M_ * C_];
__device__ float g_kt[(size_t)M_ * C_];
__device__ float g_vt[(size_t)M_ * C_];
__device__ float g_qh[(size_t)B_ * H_ * T_ * D_];
__device__ float g_kh[(size_t)B_ * H_ * T_ * D_];
__device__ float g_vh[(size_t)B_ * H_ * T_ * D_];
__device__ float g_yt[(size_t)M_ * C_];

// ---------------- tf32 GEMM: C[M,384] = A[M,384] * B[384,384]^T ----------------
// Block tile 128x128x16, 256 threads, 8 warps as 2(m) x 4(n), warp tile 64x32.
// Smem rows hold 16 k-values permuted so (k, k+4) are adjacent -> LDS.64 frags.
#define TBM 128
#define TBN 128
#define TBK 16
#define TSTR 24                    // floats per smem row (16 data + 8 pad)
#define NCHUNK (C_ / TBK)          // 24

__global__ __launch_bounds__(256, 2) void sgemm_tf32(const float* __restrict__ A,
                                                     const float* __restrict__ Bm,
                                                     float* __restrict__ Cm)
{
    __shared__ __align__(16) unsigned sA[2][TBM * TSTR];
    __shared__ __align__(16) unsigned sB[2][TBN * TSTR];

    const int tid  = threadIdx.x;
    const int w    = tid >> 5;
    const int lane = tid & 31;
    const int gr   = lane >> 2;    // 0..7
    const int gc   = lane & 3;     // 0..3
    const int wm   = w >> 2;       // 0..1  -> m offset wm*64
    const int wn   = w & 3;        // 0..3  -> n offset wn*32

    const int m0 = blockIdx.y * TBM;
    const int n0 = blockIdx.x * TBN;

    const int lr = tid >> 1;              // 0..127 row within tile
    const int lk = (tid & 1) * 8;         // 0 or 8: k-subblock

    const float* Ag = A  + (size_t)(m0 + lr) * C_ + lk;
    const float* Bg = Bm + (size_t)(n0 + lr) * C_ + lk;

    float acc[4][4][4];
#pragma unroll
    for (int i = 0; i < 4; i++)
#pragma unroll
        for (int j = 0; j < 4; j++)
#pragma unroll
            for (int r = 0; r < 4; r++) acc[i][j][r] = 0.f;

    float4 av0, av1, bv0, bv1;

    // prologue: load + store chunk 0
    av0 = *(const float4*)(Ag);     av1 = *(const float4*)(Ag + 4);
    bv0 = *(const float4*)(Bg);     bv1 = *(const float4*)(Bg + 4);
    {
        unsigned* da = sA[0] + lr * TSTR + lk;
        da[0] = cvt_tf32(av0.x); da[2] = cvt_tf32(av0.y);
        da[4] = cvt_tf32(av0.z); da[6] = cvt_tf32(av0.w);
        da[1] = cvt_tf32(av1.x); da[3] = cvt_tf32(av1.y);
        da[5] = cvt_tf32(av1.z); da[7] = cvt_tf32(av1.w);
        unsigned* db = sB[0] + lr * TSTR + lk;
        db[0] = cvt_tf32(bv0.x); db[2] = cvt_tf32(bv0.y);
        db[4] = cvt_tf32(bv0.z); db[6] = cvt_tf32(bv0.w);
        db[1] = cvt_tf32(bv1.x); db[3] = cvt_tf32(bv1.y);
        db[5] = cvt_tf32(bv1.z); db[7] = cvt_tf32(bv1.w);
    }
    __syncthreads();

    for (int ch = 0; ch < NCHUNK; ch++) {
        const int cur = ch & 1;
        const bool more = (ch + 1) < NCHUNK;
        if (more) {
            const float* Ap = Ag + (ch + 1) * TBK;
            const float* Bp = Bg + (ch + 1) * TBK;
            av0 = *(const float4*)(Ap);     av1 = *(const float4*)(Ap + 4);
            bv0 = *(const float4*)(Bp);     bv1 = *(const float4*)(Bp + 4);
        }

        // MMA over current buffer: 2 k-steps of 8
#pragma unroll
        for (int s = 0; s < 2; s++) {
            unsigned a[4][4];
#pragma unroll
            for (int i = 0; i < 4; i++) {
                const uint2 lo = *(const uint2*)(sA[cur] + (wm*64 + i*16 + gr    ) * TSTR + s*8 + gc*2);
                const uint2 hi = *(const uint2*)(sA[cur] + (wm*64 + i*16 + gr + 8) * TSTR + s*8 + gc*2);
                a[i][0] = lo.x; a[i][1] = hi.x; a[i][2] = lo.y; a[i][3] = hi.y;
            }
            unsigned b[4][2];
#pragma unroll
            for (int j = 0; j < 4; j++) {
                const uint2 bb = *(const uint2*)(sB[cur] + (wn*32 + j*8 + gr) * TSTR + s*8 + gc*2);
                b[j][0] = bb.x; b[j][1] = bb.y;
            }
#pragma unroll
            for (int i = 0; i < 4; i++)
#pragma unroll
                for (int j = 0; j < 4; j++)
                    mma8(acc[i][j], a[i], b[j][0], b[j][1]);
        }

        if (more) {
            const int nxt = cur ^ 1;
            unsigned* da = sA[nxt] + lr * TSTR + lk;
            da[0] = cvt_tf32(av0.x); da[2] = cvt_tf32(av0.y);
            da[4] = cvt_tf32(av0.z); da[6] = cvt_tf32(av0.w);
            da[1] = cvt_tf32(av1.x); da[3] = cvt_tf32(av1.y);
            da[5] = cvt_tf32(av1.z); da[7] = cvt_tf32(av1.w);
            unsigned* db = sB[nxt] + lr * TSTR + lk;
            db[0] = cvt_tf32(bv0.x); db[2] = cvt_tf32(bv0.y);
            db[4] = cvt_tf32(bv0.z); db[6] = cvt_tf32(bv0.w);
            db[1] = cvt_tf32(bv1.x); db[3] = cvt_tf32(bv1.y);
            db[5] = cvt_tf32(bv1.z); db[7] = cvt_tf32(bv1.w);
        }
        __syncthreads();
    }

    // epilogue
#pragma unroll
    for (int i = 0; i < 4; i++) {
#pragma unroll
        for (int j = 0; j < 4; j++) {
            const int r  = m0 + wm*64 + i*16 + gr;
            const int cc = n0 + wn*32 + j*8 + gc*2;
            *(float2*)(Cm + (size_t)r * C_ + cc)       = make_float2(acc[i][j][0], acc[i][j][1]);
            *(float2*)(Cm + (size_t)(r + 8) * C_ + cc) = make_float2(acc[i][j][2], acc[i][j][3]);
        }
    }
}

// ---------------- RoPE + RMS-norm + transpose ----------------
__global__ __launch_bounds__(256) void rope_rms_kernel(const float* __restrict__ cosp,
                                                       const float* __restrict__ sinp)
{
    const int gwarp = (blockIdx.x * blockDim.x + threadIdx.x) >> 5;
    const int lane  = threadIdx.x & 31;
    if (gwarp >= B_ * T_ * H_) return;

    const int h  = gwarp % H_;
    const int bt = gwarp / H_;
    const int t  = bt % T_;
    const int b  = bt / T_;

    const size_t src_off = (size_t)bt * C_ + h * D_;
    const size_t dst_off = ((size_t)(b * H_ + h) * T_ + t) * D_;

    const float c = cosp[t * HALF_ + lane];
    const float s = sinp[t * HALF_ + lane];

    {
        const float x1 = g_qt[src_off + lane];
        const float x2 = g_qt[src_off + lane + HALF_];
        const float y1 =  x1 * c + x2 * s;
        const float y2 = -x1 * s + x2 * c;
        float ss = y1 * y1 + y2 * y2;
#pragma unroll
        for (int o = 16; o; o >>= 1) ss += __shfl_xor_sync(0xffffffffu, ss, o);
        const float r = rsqrtf(ss * (1.f / 64.f) + 1e-5f);
        g_qh[dst_off + lane]         = y1 * r;
        g_qh[dst_off + lane + HALF_] = y2 * r;
    }
    {
        const float x1 = g_kt[src_off + lane];
        const float x2 = g_kt[src_off + lane + HALF_];
        const float y1 =  x1 * c + x2 * s;
        const float y2 = -x1 * s + x2 * c;
        float ss = y1 * y1 + y2 * y2;
#pragma unroll
        for (int o = 16; o; o >>= 1) ss += __shfl_xor_sync(0xffffffffu, ss, o);
        const float r = rsqrtf(ss * (1.f / 64.f) + 1e-5f);
        g_kh[dst_off + lane]         = y1 * r;
        g_kh[dst_off + lane + HALF_] = y2 * r;
    }
    g_vh[dst_off + lane]         = g_vt[src_off + lane];
    g_vh[dst_off + lane + HALF_] = g_vt[src_off + lane + HALF_];
}

// ---------------- attention: flash, tf32 mma.sync ----------------
#define AQ 128
#define AK 64
#define KSTR 68
#define VSTR 72
#define PSTR 68
#define ASMEM ((64*KSTR + 64*VSTR + 4*32*PSTR) * 4)

__global__ __launch_bounds__(128) void attn_mma()
{
    extern __shared__ float smf[];
    float* Ks = smf;                        // [64][KSTR]
    float* Vs = smf + 64*KSTR;              // [64][VSTR]
    const int tid  = threadIdx.x;
    const int w    = tid >> 5;
    const int lane = tid & 31;
    const int gr   = lane >> 2;
    const int gc   = lane & 3;
    float* Ps = smf + 64*KSTR + 64*VSTR + w * (32*PSTR);

    const int bh = blockIdx.y;
    const int q0 = blockIdx.x * AQ + w * 32;

    const float* Qg = g_qh + ((size_t)bh * T_ + q0) * D_;
    const float* Kg = g_kh + (size_t)bh * T_ * D_;
    const float* Vg = g_vh + (size_t)bh * T_ * D_;

    const float qsc = 0.125f * 1.44269504088896340736f;
    unsigned qa[2][8][4];
#pragma unroll
    for (int hm = 0; hm < 2; hm++) {
        const float* qr0 = Qg + (hm*16 + gr) * D_;
        const float* qr1 = qr0 + 8 * D_;
#pragma unroll
        for (int kc = 0; kc < 8; kc++) {
            qa[hm][kc][0] = cvt_tf32(qr0[kc*8 + gc]     * qsc);
            qa[hm][kc][1] = cvt_tf32(qr1[kc*8 + gc]     * qsc);
            qa[hm][kc][2] = cvt_tf32(qr0[kc*8 + gc + 4] * qsc);
            qa[hm][kc][3] = cvt_tf32(qr1[kc*8 + gc + 4] * qsc);
        }
    }

    float o[2][8][4];
#pragma unroll
    for (int hm = 0; hm < 2; hm++)
#pragma unroll
        for (int nt = 0; nt < 8; nt++)
#pragma unroll
            for (int j = 0; j < 4; j++) o[hm][nt][j] = 0.f;

    float mrow[2][2] = {{-1e30f, -1e30f}, {-1e30f, -1e30f}};
    float lrow[2][2] = {{0.f, 0.f}, {0.f, 0.f}};

    for (int s0 = 0; s0 < T_; s0 += AK) {
        __syncthreads();
#pragma unroll
        for (int i = tid; i < 1024; i += 128) {
            const int r = i >> 4, c = (i & 15) * 4;
            const float4 kq = *(const float4*)(Kg + (size_t)(s0 + r) * D_ + c);
            float* kd = Ks + r * KSTR + c;
            kd[0] = tf32f(kq.x); kd[1] = tf32f(kq.y);
            kd[2] = tf32f(kq.z); kd[3] = tf32f(kq.w);
            const float4 vq = *(const float4*)(Vg + (size_t)(s0 + r) * D_ + c);
            float* vd = Vs + r * VSTR + c;
            vd[0] = tf32f(vq.x); vd[1] = tf32f(vq.y);
            vd[2] = tf32f(vq.z); vd[3] = tf32f(vq.w);
        }
        __syncthreads();

        float sv[2][8][4];
#pragma unroll
        for (int hm = 0; hm < 2; hm++)
#pragma unroll
            for (int nt = 0; nt < 8; nt++)
#pragma unroll
                for (int j = 0; j < 4; j++) sv[hm][nt][j] = 0.f;

#pragma unroll
        for (int nt = 0; nt < 8; nt++) {
            const float* kb = Ks + (nt*8 + gr) * KSTR + gc;
            unsigned bl[8][2];
#pragma unroll
            for (int kc = 0; kc < 8; kc++) {
                bl[kc][0] = __float_as_uint(kb[kc*8]);
                bl[kc][1] = __float_as_uint(kb[kc*8 + 4]);
            }
#pragma unroll
            for (int kc = 0; kc < 8; kc++) mma8(sv[0][nt], qa[0][kc], bl[kc][0], bl[kc][1]);
#pragma unroll
            for (int kc = 0; kc < 8; kc++) mma8(sv[1][nt], qa[1][kc], bl[kc][0], bl[kc][1]);
        }

        __syncwarp();
#pragma unroll
        for (int hm = 0; hm < 2; hm++) {
            float mx0 = -1e30f, mx1 = -1e30f;
#pragma unroll
            for (int nt = 0; nt < 8; nt++) {
                mx0 = fmaxf(mx0, fmaxf(sv[hm][nt][0], sv[hm][nt][1]));
                mx1 = fmaxf(mx1, fmaxf(sv[hm][nt][2], sv[hm][nt][3]));
            }
#pragma unroll
            for (int off = 1; off <= 2; off <<= 1) {
                mx0 = fmaxf(mx0, __shfl_xor_sync(0xffffffffu, mx0, off));
                mx1 = fmaxf(mx1, __shfl_xor_sync(0xffffffffu, mx1, off));
            }
            const float nm0 = fmaxf(mrow[hm][0], mx0);
            const float nm1 = fmaxf(mrow[hm][1], mx1);
            const float c0 = ex2f(mrow[hm][0] - nm0);
            const float c1 = ex2f(mrow[hm][1] - nm1);
            mrow[hm][0] = nm0; mrow[hm][1] = nm1;
            lrow[hm][0] *= c0; lrow[hm][1] *= c1;

            float rs0 = 0.f, rs1 = 0.f;
#pragma unroll
            for (int nt = 0; nt < 8; nt++) {
                const float p00 = ex2f(sv[hm][nt][0] - nm0);
                const float p01 = ex2f(sv[hm][nt][1] - nm0);
                const float p10 = ex2f(sv[hm][nt][2] - nm1);
                const float p11 = ex2f(sv[hm][nt][3] - nm1);
                rs0 += p00 + p01;
                rs1 += p10 + p11;
                float* pr0 = Ps + (hm*16 + gr) * PSTR + nt*8 + 2*gc;
                pr0[0] = tf32f(p00); pr0[1] = tf32f(p01);
                float* pr1 = pr0 + 8 * PSTR;
                pr1[0] = tf32f(p10); pr1[1] = tf32f(p11);
            }
#pragma unroll
            for (int off = 1; off <= 2; off <<= 1) {
                rs0 += __shfl_xor_sync(0xffffffffu, rs0, off);
                rs1 += __shfl_xor_sync(0xffffffffu, rs1, off);
            }
            lrow[hm][0] += rs0; lrow[hm][1] += rs1;
#pragma unroll
            for (int nt = 0; nt < 8; nt++) {
                o[hm][nt][0] *= c0; o[hm][nt][1] *= c0;
                o[hm][nt][2] *= c1; o[hm][nt][3] *= c1;
            }
        }
        __syncwarp();

#pragma unroll
        for (int kc = 0; kc < 8; kc++) {
            unsigned a0[4], a1[4];
            const float* pb = Ps + gr * PSTR + kc*8 + gc;
            a0[0] = __float_as_uint(pb[0]);
            a0[1] = __float_as_uint(pb[8*PSTR]);
            a0[2] = __float_as_uint(pb[4]);
            a0[3] = __float_as_uint(pb[8*PSTR + 4]);
            const float* pb1 = pb + 16*PSTR;
            a1[0] = __float_as_uint(pb1[0]);
            a1[1] = __float_as_uint(pb1[8*PSTR]);
            a1[2] = __float_as_uint(pb1[4]);
            a1[3] = __float_as_uint(pb1[8*PSTR + 4]);
#pragma unroll
            for (int nt = 0; nt < 8; nt++) {
                const float* vb = Vs + (kc*8 + gc) * VSTR + nt*8 + gr;
                const unsigned b0 = __float_as_uint(vb[0]);
                const unsigned b1 = __float_as_uint(vb[4*VSTR]);
                mma8(o[0][nt], a0, b0, b1);
                mma8(o[1][nt], a1, b0, b1);
            }
        }
        __syncwarp();
    }

    const int b = bh / H_;
    const int h = bh % H_;
#pragma unroll
    for (int hm = 0; hm < 2; hm++) {
        const float il0 = 1.f / lrow[hm][0];
        const float il1 = 1.f / lrow[hm][1];
        const int r0 = q0 + hm*16 + gr;
        const int r1 = r0 + 8;
#pragma unroll
        for (int nt = 0; nt < 8; nt++) {
            const int col = h * D_ + nt*8 + 2*gc;
            *(float2*)(g_yt + (size_t)(b * T_ + r0) * C_ + col) =
                make_float2(o[hm][nt][0] * il0, o[hm][nt][1] * il0);
            *(float2*)(g_yt + (size_t)(b * T_ + r1) * C_ + col) =
                make_float2(o[hm][nt][2] * il1, o[hm][nt][3] * il1);
        }
    }
}

// ---------------- launch ----------------
extern "C" void kernel_launch(void* const* d_in, const int* in_sizes, int n_in,
                              void* d_out, int out_size)
{
    const float* x    = (const float*)d_in[0];
    const float* Wq   = (const float*)d_in[1];
    const float* Wk   = (const float*)d_in[2];
    const float* Wv   = (const float*)d_in[3];
    const float* Wo   = (const float*)d_in[4];
    const float* cosp = (const float*)d_in[5];
    const float* sinp = (const float*)d_in[6];
    float* out = (float*)d_out;

    void *p_qt, *p_kt, *p_vt, *p_yt;
    cudaGetSymbolAddress(&p_qt, g_qt);
    cudaGetSymbolAddress(&p_kt, g_kt);
    cudaGetSymbolAddress(&p_vt, g_vt);
    cudaGetSymbolAddress(&p_yt, g_yt);

    static int smem_set = 0;
    if (!smem_set) {
        cudaFuncSetAttribute(attn_mma, cudaFuncAttributeMaxDynamicSharedMemorySize, ASMEM);
        smem_set = 1;
    }

    dim3 gg(C_ / TBN, M_ / TBM);   // (3, 128)
    sgemm_tf32<<<gg, 256>>>(x, Wq, (float*)p_qt);
    sgemm_tf32<<<gg, 256>>>(x, Wk, (float*)p_kt);
    sgemm_tf32<<<gg, 256>>>(x, Wv, (float*)p_vt);

    const int rows = B_ * T_ * H_;
    rope_rms_kernel<<<rows / 8, 256>>>(cosp, sinp);

    dim3 ga(T_ / AQ, B_ * H_);                // (16, 48)
    attn_mma<<<ga, 128, ASMEM>>>();

    sgemm_tf32<<<gg, 256>>>((const float*)p_yt, Wo, out);
}

// round 5
// speedup vs baseline: 7.3081x; 1.0286x over previous
#include <cuda_runtime.h>
#include <math.h>

// Problem constants
#define B_ 8
#define T_ 2048
#define C_ 384
#define H_ 6
#define D_ 64
#define M_ (B_*T_)          // 16384 rows
#define HALF_ 32            // D/2

// ---------------- tf32 helpers ----------------
__device__ __forceinline__ unsigned cvt_tf32(float x) {
    unsigned u;
    asm("cvt.rna.tf32.f32 %0, %1;" : "=r"(u) : "f"(x));
    return u;
}
__device__ __forceinline__ float tf32f(float x) {
    return __uint_as_float(cvt_tf32(x));
}
__device__ __forceinline__ float ex2f(float x) {
    float y;
    asm("ex2.approx.f32 %0, %1;" : "=f"(y) : "f"(x));
    return y;
}
__device__ __forceinline__ void mma8(float c[4], const unsigned a[4],
                                     unsigned b0, unsigned b1) {
    asm volatile(
        "mma.sync.aligned.m16n8k8.row.col.f32.tf32.tf32.f32 "
        "{%0,%1,%2,%3}, {%4,%5,%6,%7}, {%8,%9}, {%0,%1,%2,%3};"
        : "+f"(c[0]), "+f"(c[1]), "+f"(c[2]), "+f"(c[3])
        : "r"(a[0]), "r"(a[1]), "r"(a[2]), "r"(a[3]), "r"(b0), "r"(b1));
}

// ---------------- scratch ----------------
__device__ float g_qt[(size_t)M_ * C_];
__device__ float g_kt[(size_t)M_ * C_];
__device__ float g_vt[(size_t)M_ * C_];
__device__ float g_qh[(size_t)B_ * H_ * T_ * D_];
__device__ float g_kh[(size_t)B_ * H_ * T_ * D_];
__device__ float g_vh[(size_t)B_ * H_ * T_ * D_];
__device__ float g_yt[(size_t)M_ * C_];
__device__ float g_xc[(size_t)M_ * C_];       // tf32-rounded x
__device__ float g_wq[(size_t)C_ * C_];       // tf32-rounded weights
__device__ float g_wk[(size_t)C_ * C_];
__device__ float g_wv[(size_t)C_ * C_];
__device__ float g_wo[(size_t)C_ * C_];

// ---------------- elementwise tf32 pre-convert ----------------
__global__ __launch_bounds__(256) void cvt_kernel(const float4* __restrict__ src,
                                                  float4* __restrict__ dst, int n4)
{
    const int i = blockIdx.x * blockDim.x + threadIdx.x;
    if (i < n4) {
        const float4 v = src[i];
        dst[i] = make_float4(tf32f(v.x), tf32f(v.y), tf32f(v.z), tf32f(v.w));
    }
}

// ---------------- tf32 GEMM: C[M,384] = A[M,384] * B[384,384]^T ----------------
// Inputs pre-rounded to tf32. Block tile 128x128x16, 256 threads, 8 warps 2x4,
// warp tile 64x32. Smem rows hold 16 k-values permuted so (k, k+4) adjacent.
#define TBM 128
#define TBN 128
#define TBK 16
#define TSTR 24
#define NCHUNK (C_ / TBK)          // 24

__device__ __forceinline__ uint4 perm_lo(float4 v0, float4 v1) {
    return make_uint4(__float_as_uint(v0.x), __float_as_uint(v1.x),
                      __float_as_uint(v0.y), __float_as_uint(v1.y));
}
__device__ __forceinline__ uint4 perm_hi(float4 v0, float4 v1) {
    return make_uint4(__float_as_uint(v0.z), __float_as_uint(v1.z),
                      __float_as_uint(v0.w), __float_as_uint(v1.w));
}

__global__ __launch_bounds__(256, 2) void sgemm_tf32(const float* __restrict__ A,
                                                     const float* __restrict__ Bm,
                                                     float* __restrict__ Cm)
{
    __shared__ __align__(16) unsigned sA[2][TBM * TSTR];
    __shared__ __align__(16) unsigned sB[2][TBN * TSTR];

    const int tid  = threadIdx.x;
    const int w    = tid >> 5;
    const int lane = tid & 31;
    const int gr   = lane >> 2;
    const int gc   = lane & 3;
    const int wm   = w >> 2;
    const int wn   = w & 3;

    const int m0 = blockIdx.y * TBM;
    const int n0 = blockIdx.x * TBN;

    const int lr = tid >> 1;
    const int lk = (tid & 1) * 8;

    const float* Ag = A  + (size_t)(m0 + lr) * C_ + lk;
    const float* Bg = Bm + (size_t)(n0 + lr) * C_ + lk;

    float acc[4][4][4];
#pragma unroll
    for (int i = 0; i < 4; i++)
#pragma unroll
        for (int j = 0; j < 4; j++)
#pragma unroll
            for (int r = 0; r < 4; r++) acc[i][j][r] = 0.f;

    float4 av0, av1, bv0, bv1;

    av0 = *(const float4*)(Ag);     av1 = *(const float4*)(Ag + 4);
    bv0 = *(const float4*)(Bg);     bv1 = *(const float4*)(Bg + 4);
    *(uint4*)(sA[0] + lr * TSTR + lk)     = perm_lo(av0, av1);
    *(uint4*)(sA[0] + lr * TSTR + lk + 4) = perm_hi(av0, av1);
    *(uint4*)(sB[0] + lr * TSTR + lk)     = perm_lo(bv0, bv1);
    *(uint4*)(sB[0] + lr * TSTR + lk + 4) = perm_hi(bv0, bv1);
    __syncthreads();

    for (int ch = 0; ch < NCHUNK; ch++) {
        const int cur = ch & 1;
        const bool more = (ch + 1) < NCHUNK;
        if (more) {
            const float* Ap = Ag + (ch + 1) * TBK;
            const float* Bp = Bg + (ch + 1) * TBK;
            av0 = *(const float4*)(Ap);     av1 = *(const float4*)(Ap + 4);
            bv0 = *(const float4*)(Bp);     bv1 = *(const float4*)(Bp + 4);
        }

#pragma unroll
        for (int s = 0; s < 2; s++) {
            unsigned a[4][4];
#pragma unroll
            for (int i = 0; i < 4; i++) {
                const uint2 lo = *(const uint2*)(sA[cur] + (wm*64 + i*16 + gr    ) * TSTR + s*8 + gc*2);
                const uint2 hi = *(const uint2*)(sA[cur] + (wm*64 + i*16 + gr + 8) * TSTR + s*8 + gc*2);
                a[i][0] = lo.x; a[i][1] = hi.x; a[i][2] = lo.y; a[i][3] = hi.y;
            }
            unsigned b[4][2];
#pragma unroll
            for (int j = 0; j < 4; j++) {
                const uint2 bb = *(const uint2*)(sB[cur] + (wn*32 + j*8 + gr) * TSTR + s*8 + gc*2);
                b[j][0] = bb.x; b[j][1] = bb.y;
            }
#pragma unroll
            for (int i = 0; i < 4; i++)
#pragma unroll
                for (int j = 0; j < 4; j++)
                    mma8(acc[i][j], a[i], b[j][0], b[j][1]);
        }

        if (more) {
            const int nxt = cur ^ 1;
            *(uint4*)(sA[nxt] + lr * TSTR + lk)     = perm_lo(av0, av1);
            *(uint4*)(sA[nxt] + lr * TSTR + lk + 4) = perm_hi(av0, av1);
            *(uint4*)(sB[nxt] + lr * TSTR + lk)     = perm_lo(bv0, bv1);
            *(uint4*)(sB[nxt] + lr * TSTR + lk + 4) = perm_hi(bv0, bv1);
        }
        __syncthreads();
    }

#pragma unroll
    for (int i = 0; i < 4; i++) {
#pragma unroll
        for (int j = 0; j < 4; j++) {
            const int r  = m0 + wm*64 + i*16 + gr;
            const int cc = n0 + wn*32 + j*8 + gc*2;
            *(float2*)(Cm + (size_t)r * C_ + cc)       = make_float2(acc[i][j][0], acc[i][j][1]);
            *(float2*)(Cm + (size_t)(r + 8) * C_ + cc) = make_float2(acc[i][j][2], acc[i][j][3]);
        }
    }
}

// ---------------- RoPE + RMS-norm + transpose (writes tf32-rounded) ----------------
__global__ __launch_bounds__(256) void rope_rms_kernel(const float* __restrict__ cosp,
                                                       const float* __restrict__ sinp)
{
    const int gwarp = (blockIdx.x * blockDim.x + threadIdx.x) >> 5;
    const int lane  = threadIdx.x & 31;
    if (gwarp >= B_ * T_ * H_) return;

    const int h  = gwarp % H_;
    const int bt = gwarp / H_;
    const int t  = bt % T_;
    const int b  = bt / T_;

    const size_t src_off = (size_t)bt * C_ + h * D_;
    const size_t dst_off = ((size_t)(b * H_ + h) * T_ + t) * D_;

    const float c = cosp[t * HALF_ + lane];
    const float s = sinp[t * HALF_ + lane];
    const float qsc = 0.125f * 1.44269504088896340736f;  // 1/sqrt(D) * log2(e)

    {
        const float x1 = g_qt[src_off + lane];
        const float x2 = g_qt[src_off + lane + HALF_];
        const float y1 =  x1 * c + x2 * s;
        const float y2 = -x1 * s + x2 * c;
        float ss = y1 * y1 + y2 * y2;
#pragma unroll
        for (int o = 16; o; o >>= 1) ss += __shfl_xor_sync(0xffffffffu, ss, o);
        const float r = rsqrtf(ss * (1.f / 64.f) + 1e-5f) * qsc;
        g_qh[dst_off + lane]         = tf32f(y1 * r);
        g_qh[dst_off + lane + HALF_] = tf32f(y2 * r);
    }
    {
        const float x1 = g_kt[src_off + lane];
        const float x2 = g_kt[src_off + lane + HALF_];
        const float y1 =  x1 * c + x2 * s;
        const float y2 = -x1 * s + x2 * c;
        float ss = y1 * y1 + y2 * y2;
#pragma unroll
        for (int o = 16; o; o >>= 1) ss += __shfl_xor_sync(0xffffffffu, ss, o);
        const float r = rsqrtf(ss * (1.f / 64.f) + 1e-5f);
        g_kh[dst_off + lane]         = tf32f(y1 * r);
        g_kh[dst_off + lane + HALF_] = tf32f(y2 * r);
    }
    g_vh[dst_off + lane]         = tf32f(g_vt[src_off + lane]);
    g_vh[dst_off + lane + HALF_] = tf32f(g_vt[src_off + lane + HALF_]);
}

// ---------------- attention: flash, tf32 mma.sync, max-free softmax ----------------
// Safe because post-rms |q|=|k|=8 exactly => |logit*log2e| <= 11.54.
#define AQ 128
#define AK 64
#define KSTR 68
#define VSTR 72
#define PSTR 68
#define ASMEM ((64*KSTR + 64*VSTR + 4*32*PSTR) * 4)

__global__ __launch_bounds__(128) void attn_mma()
{
    extern __shared__ float smf[];
    float* Ks = smf;                        // [64][KSTR]
    float* Vs = smf + 64*KSTR;              // [64][VSTR]
    const int tid  = threadIdx.x;
    const int w    = tid >> 5;
    const int lane = tid & 31;
    const int gr   = lane >> 2;
    const int gc   = lane & 3;
    float* Ps = smf + 64*KSTR + 64*VSTR + w * (32*PSTR);

    const int bh = blockIdx.y;
    const int q0 = blockIdx.x * AQ + w * 32;

    const float* Qg = g_qh + ((size_t)bh * T_ + q0) * D_;
    const float* Kg = g_kh + (size_t)bh * T_ * D_;
    const float* Vg = g_vh + (size_t)bh * T_ * D_;

    // Q fragments: already scaled + tf32-rounded in rope kernel
    unsigned qa[2][8][4];
#pragma unroll
    for (int hm = 0; hm < 2; hm++) {
        const float* qr0 = Qg + (hm*16 + gr) * D_;
        const float* qr1 = qr0 + 8 * D_;
#pragma unroll
        for (int kc = 0; kc < 8; kc++) {
            qa[hm][kc][0] = __float_as_uint(qr0[kc*8 + gc]);
            qa[hm][kc][1] = __float_as_uint(qr1[kc*8 + gc]);
            qa[hm][kc][2] = __float_as_uint(qr0[kc*8 + gc + 4]);
            qa[hm][kc][3] = __float_as_uint(qr1[kc*8 + gc + 4]);
        }
    }

    float o[2][8][4];
#pragma unroll
    for (int hm = 0; hm < 2; hm++)
#pragma unroll
        for (int nt = 0; nt < 8; nt++)
#pragma unroll
            for (int j = 0; j < 4; j++) o[hm][nt][j] = 0.f;

    float lrow[2][2] = {{0.f, 0.f}, {0.f, 0.f}};

    for (int s0 = 0; s0 < T_; s0 += AK) {
        __syncthreads();
        // pure float4 copies (K/V already tf32-rounded)
#pragma unroll
        for (int i = tid; i < 1024; i += 128) {
            const int r = i >> 4, c = (i & 15) * 4;
            *(float4*)(Ks + r * KSTR + c) = *(const float4*)(Kg + (size_t)(s0 + r) * D_ + c);
            *(float4*)(Vs + r * VSTR + c) = *(const float4*)(Vg + (size_t)(s0 + r) * D_ + c);
        }
        __syncthreads();

        // ---- S = Q K^T ----
        float sv[2][8][4];
#pragma unroll
        for (int hm = 0; hm < 2; hm++)
#pragma unroll
            for (int nt = 0; nt < 8; nt++)
#pragma unroll
                for (int j = 0; j < 4; j++) sv[hm][nt][j] = 0.f;

#pragma unroll
        for (int nt = 0; nt < 8; nt++) {
            const float* kb = Ks + (nt*8 + gr) * KSTR + gc;
            unsigned bl[8][2];
#pragma unroll
            for (int kc = 0; kc < 8; kc++) {
                bl[kc][0] = __float_as_uint(kb[kc*8]);
                bl[kc][1] = __float_as_uint(kb[kc*8 + 4]);
            }
#pragma unroll
            for (int kc = 0; kc < 8; kc++) mma8(sv[0][nt], qa[0][kc], bl[kc][0], bl[kc][1]);
#pragma unroll
            for (int kc = 0; kc < 8; kc++) mma8(sv[1][nt], qa[1][kc], bl[kc][0], bl[kc][1]);
        }

        // ---- p = exp2(s); accumulate l; stage P ----
#pragma unroll
        for (int hm = 0; hm < 2; hm++) {
#pragma unroll
            for (int nt = 0; nt < 8; nt++) {
                const float p00 = ex2f(sv[hm][nt][0]);
                const float p01 = ex2f(sv[hm][nt][1]);
                const float p10 = ex2f(sv[hm][nt][2]);
                const float p11 = ex2f(sv[hm][nt][3]);
                lrow[hm][0] += p00 + p01;
                lrow[hm][1] += p10 + p11;
                float* pr0 = Ps + (hm*16 + gr) * PSTR + nt*8 + 2*gc;
                pr0[0] = tf32f(p00); pr0[1] = tf32f(p01);
                float* pr1 = pr0 + 8 * PSTR;
                pr1[0] = tf32f(p10); pr1[1] = tf32f(p11);
            }
        }
        __syncwarp();

        // ---- O += P V ----
#pragma unroll
        for (int kc = 0; kc < 8; kc++) {
            unsigned a0[4], a1[4];
            const float* pb = Ps + gr * PSTR + kc*8 + gc;
            a0[0] = __float_as_uint(pb[0]);
            a0[1] = __float_as_uint(pb[8*PSTR]);
            a0[2] = __float_as_uint(pb[4]);
            a0[3] = __float_as_uint(pb[8*PSTR + 4]);
            const float* pb1 = pb + 16*PSTR;
            a1[0] = __float_as_uint(pb1[0]);
            a1[1] = __float_as_uint(pb1[8*PSTR]);
            a1[2] = __float_as_uint(pb1[4]);
            a1[3] = __float_as_uint(pb1[8*PSTR + 4]);
#pragma unroll
            for (int nt = 0; nt < 8; nt++) {
                const float* vb = Vs + (kc*8 + gc) * VSTR + nt*8 + gr;
                const unsigned b0 = __float_as_uint(vb[0]);
                const unsigned b1 = __float_as_uint(vb[4*VSTR]);
                mma8(o[0][nt], a0, b0, b1);
                mma8(o[1][nt], a1, b0, b1);
            }
        }
    }

    // final l reduction across gc group
#pragma unroll
    for (int hm = 0; hm < 2; hm++)
#pragma unroll
        for (int off = 1; off <= 2; off <<= 1) {
            lrow[hm][0] += __shfl_xor_sync(0xffffffffu, lrow[hm][0], off);
            lrow[hm][1] += __shfl_xor_sync(0xffffffffu, lrow[hm][1], off);
        }

    const int b = bh / H_;
    const int h = bh % H_;
#pragma unroll
    for (int hm = 0; hm < 2; hm++) {
        const float il0 = 1.f / lrow[hm][0];
        const float il1 = 1.f / lrow[hm][1];
        const int r0 = q0 + hm*16 + gr;
        const int r1 = r0 + 8;
#pragma unroll
        for (int nt = 0; nt < 8; nt++) {
            const int col = h * D_ + nt*8 + 2*gc;
            *(float2*)(g_yt + (size_t)(b * T_ + r0) * C_ + col) =
                make_float2(tf32f(o[hm][nt][0] * il0), tf32f(o[hm][nt][1] * il0));
            *(float2*)(g_yt + (size_t)(b * T_ + r1) * C_ + col) =
                make_float2(tf32f(o[hm][nt][2] * il1), tf32f(o[hm][nt][3] * il1));
        }
    }
}

// ---------------- launch ----------------
extern "C" void kernel_launch(void* const* d_in, const int* in_sizes, int n_in,
                              void* d_out, int out_size)
{
    const float* x    = (const float*)d_in[0];
    const float* Wq   = (const float*)d_in[1];
    const float* Wk   = (const float*)d_in[2];
    const float* Wv   = (const float*)d_in[3];
    const float* Wo   = (const float*)d_in[4];
    const float* cosp = (const float*)d_in[5];
    const float* sinp = (const float*)d_in[6];
    float* out = (float*)d_out;

    void *p_qt, *p_kt, *p_vt, *p_yt, *p_xc, *p_wq, *p_wk, *p_wv, *p_wo;
    cudaGetSymbolAddress(&p_qt, g_qt);
    cudaGetSymbolAddress(&p_kt, g_kt);
    cudaGetSymbolAddress(&p_vt, g_vt);
    cudaGetSymbolAddress(&p_yt, g_yt);
    cudaGetSymbolAddress(&p_xc, g_xc);
    cudaGetSymbolAddress(&p_wq, g_wq);
    cudaGetSymbolAddress(&p_wk, g_wk);
    cudaGetSymbolAddress(&p_wv, g_wv);
    cudaGetSymbolAddress(&p_wo, g_wo);

    static int smem_set = 0;
    if (!smem_set) {
        cudaFuncSetAttribute(attn_mma, cudaFuncAttributeMaxDynamicSharedMemorySize, ASMEM);
        smem_set = 1;
    }

    // pre-convert inputs to tf32
    const int nx4 = (M_ * C_) / 4;          // 1572864
    const int nw4 = (C_ * C_) / 4;          // 36864
    cvt_kernel<<<(nx4 + 255) / 256, 256>>>((const float4*)x,  (float4*)p_xc, nx4);
    cvt_kernel<<<(nw4 + 255) / 256, 256>>>((const float4*)Wq, (float4*)p_wq, nw4);
    cvt_kernel<<<(nw4 + 255) / 256, 256>>>((const float4*)Wk, (float4*)p_wk, nw4);
    cvt_kernel<<<(nw4 + 255) / 256, 256>>>((const float4*)Wv, (float4*)p_wv, nw4);
    cvt_kernel<<<(nw4 + 255) / 256, 256>>>((const float4*)Wo, (float4*)p_wo, nw4);

    dim3 gg(C_ / TBN, M_ / TBM);   // (3, 128)
    sgemm_tf32<<<gg, 256>>>((const float*)p_xc, (const float*)p_wq, (float*)p_qt);
    sgemm_tf32<<<gg, 256>>>((const float*)p_xc, (const float*)p_wk, (float*)p_kt);
    sgemm_tf32<<<gg, 256>>>((const float*)p_xc, (const float*)p_wv, (float*)p_vt);

    const int rows = B_ * T_ * H_;
    rope_rms_kernel<<<rows / 8, 256>>>(cosp, sinp);

    dim3 ga(T_ / AQ, B_ * H_);                // (16, 48)
    attn_mma<<<ga, 128, ASMEM>>>();

    sgemm_tf32<<<gg, 256>>>((const float*)p_yt, (const float*)p_wo, out);
}

// round 7
// speedup vs baseline: 8.1820x; 1.1196x over previous
#include <cuda_runtime.h>
#include <math.h>
#include <stdint.h>

// Problem constants
#define B_ 8
#define T_ 2048
#define C_ 384
#define H_ 6
#define D_ 64
#define M_ (B_*T_)          // 16384 rows
#define HALF_ 32            // D/2
#define MC_ (M_*C_)
#define CC_ (C_*C_)

// ---------------- tf32 helpers ----------------
__device__ __forceinline__ unsigned cvt_tf32(float x) {
    unsigned u;
    asm("cvt.rna.tf32.f32 %0, %1;" : "=r"(u) : "f"(x));
    return u;
}
__device__ __forceinline__ float tf32f(float x) {
    return __uint_as_float(cvt_tf32(x));
}
__device__ __forceinline__ float ex2f(float x) {
    float y;
    asm("ex2.approx.f32 %0, %1;" : "=f"(y) : "f"(x));
    return y;
}
__device__ __forceinline__ void mma8(float c[4], const unsigned a[4],
                                     unsigned b0, unsigned b1) {
    asm volatile(
        "mma.sync.aligned.m16n8k8.row.col.f32.tf32.tf32.f32 "
        "{%0,%1,%2,%3}, {%4,%5,%6,%7}, {%8,%9}, {%0,%1,%2,%3};"
        : "+f"(c[0]), "+f"(c[1]), "+f"(c[2]), "+f"(c[3])
        : "r"(a[0]), "r"(a[1]), "r"(a[2]), "r"(a[3]), "r"(b0), "r"(b1));
}
__device__ __forceinline__ void cp16(uint32_t dst, const void* src) {
    asm volatile("cp.async.cg.shared.global [%0], [%1], 16;" :: "r"(dst), "l"(src));
}
#define CP_COMMIT() asm volatile("cp.async.commit_group;" ::: "memory")
#define CP_WAIT1()  asm volatile("cp.async.wait_group 1;"  ::: "memory")
__device__ __forceinline__ uint32_t smem_to_u32(const void* p) {
    uint32_t a;
    asm("{ .reg .u64 t; cvta.to.shared.u64 t, %1; cvt.u32.u64 %0, t; }"
        : "=r"(a) : "l"(p));
    return a;
}

// ---------------- scratch ----------------
__device__ float g_xc[(size_t)MC_];          // tf32-rounded x
__device__ float g_w3[(size_t)3*CC_];        // tf32-rounded Wq,Wk,Wv stacked
__device__ float g_wo[(size_t)CC_];          // tf32-rounded Wo
__device__ float g_qkv[(size_t)3*MC_];       // projections (fp32)
__device__ float g_qh[(size_t)B_*H_*T_*D_];
__device__ float g_kh[(size_t)B_*H_*T_*D_];
__device__ float g_vh[(size_t)B_*H_*T_*D_];
__device__ float g_yt[(size_t)MC_];          // attention out (tf32-rounded)

// ---------------- elementwise tf32 pre-convert ----------------
__global__ __launch_bounds__(256) void cvt_kernel(const float4* __restrict__ src,
                                                  float4* __restrict__ dst, int n4)
{
    const int i = blockIdx.x * blockDim.x + threadIdx.x;
    if (i < n4) {
        const float4 v = src[i];
        dst[i] = make_float4(tf32f(v.x), tf32f(v.y), tf32f(v.z), tf32f(v.w));
    }
}

// ---------------- pipelined tf32 GEMM: C[M,384] = A[M,384] * W[384,384]^T ----------------
// 128x128x32 tiles, 256 threads, 8 warps 2(m) x 4(n), warp tile 64x32.
// 3-stage cp.async pipeline; smem row stride 36 floats (144B, 16B-aligned,
// conflict-free fragment LDS: bank = (4*gr + gc) bijection).
#define TBK 32
#define NCH (C_ / TBK)          // 12
#define NST 3
#define SSTR 36
#define STAGE_BYTES (128 * SSTR * 4)          // 18432
#define GA_OFF(st) ((st) * STAGE_BYTES)
#define GB_OFF(st) (NST * STAGE_BYTES + (st) * STAGE_BYTES)
#define GSMEM (2 * NST * STAGE_BYTES)         // 110592

__global__ __launch_bounds__(256, 2) void gemm_pipe(const float* __restrict__ A,
                                                    const float* __restrict__ W,
                                                    float* __restrict__ Cb,
                                                    int wstride, int cstride)
{
    extern __shared__ char smem[];
    const uint32_t smem_base = smem_to_u32(smem);

    const int tid  = threadIdx.x;
    const int w    = tid >> 5;
    const int lane = tid & 31;
    const int gr   = lane >> 2;
    const int gc   = lane & 3;
    const int wm   = w >> 2;          // 0..1
    const int wn   = w & 3;           // 0..3

    const int m0 = blockIdx.y * 128;
    const int n0 = blockIdx.x * 128;
    const int z  = blockIdx.z;
    const float* Wz = W + (size_t)z * wstride;
    float* Cm = Cb + (size_t)z * cstride;

    // copy mapping: idx = tid + p*256 -> row = idx>>3, seg = idx&7 (16B each)
    const int crow = tid >> 3;        // base row for p=0 (rows 0..31)
    const int cseg = tid & 7;

    float acc[4][4][4];
#pragma unroll
    for (int i = 0; i < 4; i++)
#pragma unroll
        for (int j = 0; j < 4; j++)
#pragma unroll
            for (int r = 0; r < 4; r++) acc[i][j][r] = 0.f;

    // ---- issue helper (macro-ish lambda) ----
    auto issue = [&](int ch, int st) {
#pragma unroll
        for (int p = 0; p < 4; p++) {
            const int row = crow + p * 32;
            const uint32_t doff = row * (SSTR * 4) + cseg * 16;
            cp16(smem_base + GA_OFF(st) + doff,
                 A  + (size_t)(m0 + row) * C_ + ch * TBK + cseg * 4);
            cp16(smem_base + GB_OFF(st) + doff,
                 Wz + (size_t)(n0 + row) * C_ + ch * TBK + cseg * 4);
        }
    };

    issue(0, 0); CP_COMMIT();
    issue(1, 1); CP_COMMIT();

    for (int ch = 0; ch < NCH; ch++) {
        const int st = ch % NST;
        CP_WAIT1();
        __syncthreads();

        // issue chunk ch+2 into stage (ch+2)%NST (safe: all threads finished ch-1)
        if (ch + 2 < NCH) issue(ch + 2, (ch + 2) % NST);
        CP_COMMIT();

        const unsigned* sAf = (const unsigned*)(smem + GA_OFF(st));
        const unsigned* sBf = (const unsigned*)(smem + GB_OFF(st));

#pragma unroll
        for (int s = 0; s < 4; s++) {
            unsigned a[4][4];
#pragma unroll
            for (int i = 0; i < 4; i++) {
                const int row = wm * 64 + i * 16 + gr;
                a[i][0] = sAf[row * SSTR + s * 8 + gc];
                a[i][1] = sAf[(row + 8) * SSTR + s * 8 + gc];
                a[i][2] = sAf[row * SSTR + s * 8 + gc + 4];
                a[i][3] = sAf[(row + 8) * SSTR + s * 8 + gc + 4];
            }
            unsigned b[4][2];
#pragma unroll
            for (int j = 0; j < 4; j++) {
                const int row = wn * 32 + j * 8 + gr;
                b[j][0] = sBf[row * SSTR + s * 8 + gc];
                b[j][1] = sBf[row * SSTR + s * 8 + gc + 4];
            }
#pragma unroll
            for (int i = 0; i < 4; i++)
#pragma unroll
                for (int j = 0; j < 4; j++)
                    mma8(acc[i][j], a[i], b[j][0], b[j][1]);
        }
        __syncthreads();
    }

    // epilogue
#pragma unroll
    for (int i = 0; i < 4; i++) {
#pragma unroll
        for (int j = 0; j < 4; j++) {
            const int r  = m0 + wm * 64 + i * 16 + gr;
            const int cc = n0 + wn * 32 + j * 8 + gc * 2;
            *(float2*)(Cm + (size_t)r * C_ + cc)       = make_float2(acc[i][j][0], acc[i][j][1]);
            *(float2*)(Cm + (size_t)(r + 8) * C_ + cc) = make_float2(acc[i][j][2], acc[i][j][3]);
        }
    }
}

// ---------------- RoPE + RMS-norm + transpose (writes tf32-rounded) ----------------
__global__ __launch_bounds__(256) void rope_rms_kernel(const float* __restrict__ cosp,
                                                       const float* __restrict__ sinp)
{
    const int gwarp = (blockIdx.x * blockDim.x + threadIdx.x) >> 5;
    const int lane  = threadIdx.x & 31;
    if (gwarp >= B_ * T_ * H_) return;

    const int h  = gwarp % H_;
    const int bt = gwarp / H_;
    const int t  = bt % T_;
    const int b  = bt / T_;

    const size_t src_off = (size_t)bt * C_ + h * D_;
    const size_t dst_off = ((size_t)(b * H_ + h) * T_ + t) * D_;

    const float c = cosp[t * HALF_ + lane];
    const float s = sinp[t * HALF_ + lane];
    const float qsc = 0.125f * 1.44269504088896340736f;

    {
        const float x1 = g_qkv[src_off + lane];
        const float x2 = g_qkv[src_off + lane + HALF_];
        const float y1 =  x1 * c + x2 * s;
        const float y2 = -x1 * s + x2 * c;
        float ss = y1 * y1 + y2 * y2;
#pragma unroll
        for (int o = 16; o; o >>= 1) ss += __shfl_xor_sync(0xffffffffu, ss, o);
        const float r = rsqrtf(ss * (1.f / 64.f) + 1e-5f) * qsc;
        g_qh[dst_off + lane]         = tf32f(y1 * r);
        g_qh[dst_off + lane + HALF_] = tf32f(y2 * r);
    }
    {
        const float x1 = g_qkv[(size_t)MC_ + src_off + lane];
        const float x2 = g_qkv[(size_t)MC_ + src_off + lane + HALF_];
        const float y1 =  x1 * c + x2 * s;
        const float y2 = -x1 * s + x2 * c;
        float ss = y1 * y1 + y2 * y2;
#pragma unroll
        for (int o = 16; o; o >>= 1) ss += __shfl_xor_sync(0xffffffffu, ss, o);
        const float r = rsqrtf(ss * (1.f / 64.f) + 1e-5f);
        g_kh[dst_off + lane]         = tf32f(y1 * r);
        g_kh[dst_off + lane + HALF_] = tf32f(y2 * r);
    }
    g_vh[dst_off + lane]         = tf32f(g_qkv[(size_t)2*MC_ + src_off + lane]);
    g_vh[dst_off + lane + HALF_] = tf32f(g_qkv[(size_t)2*MC_ + src_off + lane + HALF_]);
}

// ---------------- attention: flash, tf32 mma.sync, max-free softmax ----------------
#define AQ 128
#define AK 64
#define KSTR 68
#define VSTR 72
#define PSTR 68
#define ASMEM ((64*KSTR + 64*VSTR + 4*32*PSTR) * 4)

__global__ __launch_bounds__(128) void attn_mma()
{
    extern __shared__ float smf[];
    float* Ks = smf;
    float* Vs = smf + 64*KSTR;
    const int tid  = threadIdx.x;
    const int w    = tid >> 5;
    const int lane = tid & 31;
    const int gr   = lane >> 2;
    const int gc   = lane & 3;
    float* Ps = smf + 64*KSTR + 64*VSTR + w * (32*PSTR);

    const int bh = blockIdx.y;
    const int q0 = blockIdx.x * AQ + w * 32;

    const float* Qg = g_qh + ((size_t)bh * T_ + q0) * D_;
    const float* Kg = g_kh + (size_t)bh * T_ * D_;
    const float* Vg = g_vh + (size_t)bh * T_ * D_;

    unsigned qa[2][8][4];
#pragma unroll
    for (int hm = 0; hm < 2; hm++) {
        const float* qr0 = Qg + (hm*16 + gr) * D_;
        const float* qr1 = qr0 + 8 * D_;
#pragma unroll
        for (int kc = 0; kc < 8; kc++) {
            qa[hm][kc][0] = __float_as_uint(qr0[kc*8 + gc]);
            qa[hm][kc][1] = __float_as_uint(qr1[kc*8 + gc]);
            qa[hm][kc][2] = __float_as_uint(qr0[kc*8 + gc + 4]);
            qa[hm][kc][3] = __float_as_uint(qr1[kc*8 + gc + 4]);
        }
    }

    float o[2][8][4];
#pragma unroll
    for (int hm = 0; hm < 2; hm++)
#pragma unroll
        for (int nt = 0; nt < 8; nt++)
#pragma unroll
            for (int j = 0; j < 4; j++) o[hm][nt][j] = 0.f;

    float lrow[2][2] = {{0.f, 0.f}, {0.f, 0.f}};

    for (int s0 = 0; s0 < T_; s0 += AK) {
        __syncthreads();
#pragma unroll
        for (int i = tid; i < 1024; i += 128) {
            const int r = i >> 4, c = (i & 15) * 4;
            *(float4*)(Ks + r * KSTR + c) = *(const float4*)(Kg + (size_t)(s0 + r) * D_ + c);
            *(float4*)(Vs + r * VSTR + c) = *(const float4*)(Vg + (size_t)(s0 + r) * D_ + c);
        }
        __syncthreads();

        float sv[2][8][4];
#pragma unroll
        for (int hm = 0; hm < 2; hm++)
#pragma unroll
            for (int nt = 0; nt < 8; nt++)
#pragma unroll
                for (int j = 0; j < 4; j++) sv[hm][nt][j] = 0.f;

#pragma unroll
        for (int nt = 0; nt < 8; nt++) {
            const float* kb = Ks + (nt*8 + gr) * KSTR + gc;
            unsigned bl[8][2];
#pragma unroll
            for (int kc = 0; kc < 8; kc++) {
                bl[kc][0] = __float_as_uint(kb[kc*8]);
                bl[kc][1] = __float_as_uint(kb[kc*8 + 4]);
            }
#pragma unroll
            for (int kc = 0; kc < 8; kc++) mma8(sv[0][nt], qa[0][kc], bl[kc][0], bl[kc][1]);
#pragma unroll
            for (int kc = 0; kc < 8; kc++) mma8(sv[1][nt], qa[1][kc], bl[kc][0], bl[kc][1]);
        }

#pragma unroll
        for (int hm = 0; hm < 2; hm++) {
#pragma unroll
            for (int nt = 0; nt < 8; nt++) {
                const float p00 = ex2f(sv[hm][nt][0]);
                const float p01 = ex2f(sv[hm][nt][1]);
                const float p10 = ex2f(sv[hm][nt][2]);
                const float p11 = ex2f(sv[hm][nt][3]);
                lrow[hm][0] += p00 + p01;
                lrow[hm][1] += p10 + p11;
                float* pr0 = Ps + (hm*16 + gr) * PSTR + nt*8 + 2*gc;
                pr0[0] = tf32f(p00); pr0[1] = tf32f(p01);
                float* pr1 = pr0 + 8 * PSTR;
                pr1[0] = tf32f(p10); pr1[1] = tf32f(p11);
            }
        }
        __syncwarp();

#pragma unroll
        for (int kc = 0; kc < 8; kc++) {
            unsigned a0[4], a1[4];
            const float* pb = Ps + gr * PSTR + kc*8 + gc;
            a0[0] = __float_as_uint(pb[0]);
            a0[1] = __float_as_uint(pb[8*PSTR]);
            a0[2] = __float_as_uint(pb[4]);
            a0[3] = __float_as_uint(pb[8*PSTR + 4]);
            const float* pb1 = pb + 16*PSTR;
            a1[0] = __float_as_uint(pb1[0]);
            a1[1] = __float_as_uint(pb1[8*PSTR]);
            a1[2] = __float_as_uint(pb1[4]);
            a1[3] = __float_as_uint(pb1[8*PSTR + 4]);
#pragma unroll
            for (int nt = 0; nt < 8; nt++) {
                const float* vb = Vs + (kc*8 + gc) * VSTR + nt*8 + gr;
                const unsigned b0 = __float_as_uint(vb[0]);
                const unsigned b1 = __float_as_uint(vb[4*VSTR]);
                mma8(o[0][nt], a0, b0, b1);
                mma8(o[1][nt], a1, b0, b1);
            }
        }
    }

#pragma unroll
    for (int hm = 0; hm < 2; hm++)
#pragma unroll
        for (int off = 1; off <= 2; off <<= 1) {
            lrow[hm][0] += __shfl_xor_sync(0xffffffffu, lrow[hm][0], off);
            lrow[hm][1] += __shfl_xor_sync(0xffffffffu, lrow[hm][1], off);
        }

    const int b = bh / H_;
    const int h = bh % H_;
#pragma unroll
    for (int hm = 0; hm < 2; hm++) {
        const float il0 = 1.f / lrow[hm][0];
        const float il1 = 1.f / lrow[hm][1];
        const int r0 = q0 + hm*16 + gr;
        const int r1 = r0 + 8;
#pragma unroll
        for (int nt = 0; nt < 8; nt++) {
            const int col = h * D_ + nt*8 + 2*gc;
            *(float2*)(g_yt + (size_t)(b * T_ + r0) * C_ + col) =
                make_float2(tf32f(o[hm][nt][0] * il0), tf32f(o[hm][nt][1] * il0));
            *(float2*)(g_yt + (size_t)(b * T_ + r1) * C_ + col) =
                make_float2(tf32f(o[hm][nt][2] * il1), tf32f(o[hm][nt][3] * il1));
        }
    }
}

// ---------------- launch ----------------
extern "C" void kernel_launch(void* const* d_in, const int* in_sizes, int n_in,
                              void* d_out, int out_size)
{
    const float* x    = (const float*)d_in[0];
    const float* Wq   = (const float*)d_in[1];
    const float* Wk   = (const float*)d_in[2];
    const float* Wv   = (const float*)d_in[3];
    const float* Wo   = (const float*)d_in[4];
    const float* cosp = (const float*)d_in[5];
    const float* sinp = (const float*)d_in[6];
    float* out = (float*)d_out;

    void *p_xc, *p_w3, *p_wo, *p_qkv, *p_yt;
    cudaGetSymbolAddress(&p_xc, g_xc);
    cudaGetSymbolAddress(&p_w3, g_w3);
    cudaGetSymbolAddress(&p_wo, g_wo);
    cudaGetSymbolAddress(&p_qkv, g_qkv);
    cudaGetSymbolAddress(&p_yt, g_yt);

    static int attrs_set = 0;
    if (!attrs_set) {
        cudaFuncSetAttribute(attn_mma, cudaFuncAttributeMaxDynamicSharedMemorySize, ASMEM);
        cudaFuncSetAttribute(gemm_pipe, cudaFuncAttributeMaxDynamicSharedMemorySize, GSMEM);
        attrs_set = 1;
    }

    float* w3 = (float*)p_w3;

    // pre-convert inputs to tf32
    const int nx4 = MC_ / 4;
    const int nw4 = CC_ / 4;
    cvt_kernel<<<(nx4 + 255) / 256, 256>>>((const float4*)x,  (float4*)p_xc, nx4);
    cvt_kernel<<<(nw4 + 255) / 256, 256>>>((const float4*)Wq, (float4*)(w3),          nw4);
    cvt_kernel<<<(nw4 + 255) / 256, 256>>>((const float4*)Wk, (float4*)(w3 + CC_),    nw4);
    cvt_kernel<<<(nw4 + 255) / 256, 256>>>((const float4*)Wv, (float4*)(w3 + 2*CC_),  nw4);
    cvt_kernel<<<(nw4 + 255) / 256, 256>>>((const float4*)Wo, (float4*)p_wo, nw4);

    // QKV projections: one launch, z selects weight/output
    dim3 gq(C_/128, M_/128, 3);       // (3, 128, 3)
    gemm_pipe<<<gq, 256, GSMEM>>>((const float*)p_xc, w3, (float*)p_qkv, CC_, MC_);

    const int rows = B_ * T_ * H_;
    rope_rms_kernel<<<rows / 8, 256>>>(cosp, sinp);

    dim3 ga(T_ / AQ, B_ * H_);        // (16, 48)
    attn_mma<<<ga, 128, ASMEM>>>();

    // output projection
    dim3 go(C_/128, M_/128, 1);
    gemm_pipe<<<go, 256, GSMEM>>>((const float*)p_yt, (const float*)p_wo, out, 0, 0);
}